// round 9
// baseline (speedup 1.0000x reference)
#include <cuda_runtime.h>
#include <cuda_bf16.h>
#include <math.h>
#include <stdint.h>

#define NB 16
#define NN 256
#define DDIM 512
#define NH 8
#define DKH 64
#define MROWS (NB*NN)        // 4096

// ---------------- scratch ----------------
__device__ float g_wgl[NB*NH*NN*NN];
__device__ __nv_bfloat16 g_wTh[4*DDIM*DDIM];
__device__ __nv_bfloat16 g_wTl[4*DDIM*DDIM];
__device__ __nv_bfloat16 g_ah[3*MROWS*DDIM];
__device__ __nv_bfloat16 g_al[3*MROWS*DDIM];
__device__ __nv_bfloat16 g_qh[NB*NH*NN*DKH], g_ql[NB*NH*NN*DKH];
__device__ __nv_bfloat16 g_kh[NB*NH*NN*DKH], g_kl[NB*NH*NN*DKH];
__device__ __nv_bfloat16 g_vh[NB*NH*DKH*NN], g_vl[NB*NH*DKH*NN];

// =========================== helpers ================================
__device__ __forceinline__ uint32_t smem_u32(const void* p) {
    uint32_t a;
    asm("{ .reg .u64 t; cvta.to.shared.u64 t, %1; cvt.u32.u64 %0, t; }" : "=r"(a) : "l"(p));
    return a;
}
__device__ __forceinline__ void ldsm4(uint32_t* r, uint32_t addr) {
    asm volatile("ldmatrix.sync.aligned.m8n8.x4.shared.b16 {%0,%1,%2,%3}, [%4];"
                 : "=r"(r[0]), "=r"(r[1]), "=r"(r[2]), "=r"(r[3]) : "r"(addr));
}
__device__ __forceinline__ void mma16816(float* d, const uint32_t* a, uint32_t b0, uint32_t b1) {
    asm volatile("mma.sync.aligned.m16n8k16.row.col.f32.bf16.bf16.f32 "
                 "{%0,%1,%2,%3}, {%4,%5,%6,%7}, {%8,%9}, {%0,%1,%2,%3};"
                 : "+f"(d[0]), "+f"(d[1]), "+f"(d[2]), "+f"(d[3])
                 : "r"(a[0]), "r"(a[1]), "r"(a[2]), "r"(a[3]), "r"(b0), "r"(b1));
}
#define CPA16(dst, src) \
    asm volatile("cp.async.cg.shared.global [%0], [%1], 16;" :: "r"(dst), "l"(src) : "memory")
#define CPCOMMIT() asm volatile("cp.async.commit_group;" ::: "memory")
#define CPWAIT1()  asm volatile("cp.async.wait_group 1;" ::: "memory")
#define CPWAIT0()  asm volatile("cp.async.wait_group 0;" ::: "memory")

__device__ __forceinline__ void bsplit2(float x, float y, uint32_t& h, uint32_t& l) {
    __nv_bfloat162 hh = __floats2bfloat162_rn(x, y);
    float2 r = __bfloat1622float2(hh);
    __nv_bfloat162 ll = __floats2bfloat162_rn(x - r.x, y - r.y);
    h = *(uint32_t*)&hh; l = *(uint32_t*)&ll;
}
__device__ __forceinline__ void bsplit1(float x, __nv_bfloat16& h, __nv_bfloat16& l) {
    h = __float2bfloat16_rn(x);
    l = __float2bfloat16_rn(x - __bfloat162float(h));
}
__device__ __forceinline__ void ffma2(uint64_t& acc, uint64_t a, uint64_t b) {
    asm("fma.rn.f32x2 %0, %1, %2, %0;" : "+l"(acc) : "l"(a), "l"(b));
}
__device__ __forceinline__ uint64_t pack2(float x) {
    uint64_t r; asm("mov.b64 %0, {%1, %1};" : "=l"(r) : "f"(x)); return r;
}
__device__ __forceinline__ float2 unpack2(uint64_t v) {
    float2 f; asm("mov.b64 {%0, %1}, %2;" : "=f"(f.x), "=f"(f.y) : "l"(v)); return f;
}

// =================================================================================
// Weight transpose + bf16 split
// =================================================================================
__global__ __launch_bounds__(256)
void wconv_kernel(const float* __restrict__ w0, const float* __restrict__ w1,
                  const float* __restrict__ w2, const float* __restrict__ w3)
{
    __shared__ float tile[32][33];
    const float* W = (blockIdx.z == 0) ? w0 : (blockIdx.z == 1) ? w1 :
                     (blockIdx.z == 2) ? w2 : w3;
    __nv_bfloat16* Th = g_wTh + blockIdx.z * (DDIM * DDIM);
    __nv_bfloat16* Tl = g_wTl + blockIdx.z * (DDIM * DDIM);
    const int x0 = blockIdx.x * 32, y0 = blockIdx.y * 32;
    const int tx = threadIdx.x;
    #pragma unroll
    for (int r = threadIdx.y; r < 32; r += 8)
        tile[r][tx] = W[(y0 + r) * DDIM + x0 + tx];
    __syncthreads();
    #pragma unroll
    for (int r = threadIdx.y; r < 32; r += 8) {
        float v = tile[tx][r];
        __nv_bfloat16 h, l; bsplit1(v, h, l);
        Th[(x0 + r) * DDIM + y0 + tx] = h;
        Tl[(x0 + r) * DDIM + y0 + tx] = l;
    }
}

// =================================================================================
// Input split
// =================================================================================
__global__ __launch_bounds__(256)
void asplit3_kernel(const float* __restrict__ q, const float* __restrict__ k,
                    const float* __restrict__ v)
{
    const int z = blockIdx.y;
    const float* src = (z == 0) ? q : (z == 1) ? k : v;
    __nv_bfloat16* oh = g_ah + z * (MROWS * DDIM);
    __nv_bfloat16* ol = g_al + z * (MROWS * DDIM);
    const int i4 = blockIdx.x * 256 + threadIdx.x;
    float4 f = ((const float4*)src)[i4];
    uint32_t h0, l0, h1, l1;
    bsplit2(f.x, f.y, h0, l0);
    bsplit2(f.z, f.w, h1, l1);
    ((uint2*)oh)[i4] = make_uint2(h0, h1);
    ((uint2*)ol)[i4] = make_uint2(l0, l1);
}

// =================================================================================
// GEMM device body (bf16 split, 3 passes). BM=128, BN=64, BK=32, 3-stage.
// =================================================================================
#define BK 32
#define STG 3
#define ROWB 80
#define MAT_A (128*ROWB)
#define MAT_Bb (64*ROWB)
#define STG_B (2*MAT_A + 2*MAT_Bb)   // 30720
#define GDYN (STG*STG_B)             // 92160

struct GArgs {
    const __nv_bfloat16 *Ah, *Al, *Bh, *Bl;
    const float* bias[3];
    float*       C[3];
    __nv_bfloat16 *Oh[3], *Ol[3];
    float scale[3];
    int mode[3];
};

__device__ __forceinline__ void gemm_body(const GArgs& args, int gt, char* smraw)
{
    const uint32_t sb = smem_u32(smraw);
    const int t = threadIdx.x, lane = t & 31, wid = t >> 5;
    const int wm = wid & 3, wn = wid >> 2;
    const int z = gt >> 8;
    const int rem = gt & 255;
    const int r0 = (rem >> 3) * 128, c0 = (rem & 7) * 64;

    const __nv_bfloat16* pAh = args.Ah + (size_t)z * MROWS * DDIM;
    const __nv_bfloat16* pAl = args.Al + (size_t)z * MROWS * DDIM;
    const __nv_bfloat16* pBh = args.Bh + (size_t)z * DDIM * DDIM;
    const __nv_bfloat16* pBl = args.Bl + (size_t)z * DDIM * DDIM;
    const float* bias = args.bias[z];

    const int row_a = t >> 2, ch = t & 3;
    auto load_stage = [&](int kt) {
        uint32_t dstS = sb + (uint32_t)(kt % STG) * STG_B;
        int k0 = kt * BK + ch * 8;
        #pragma unroll
        for (int it = 0; it < 2; it++) {
            int row = row_a + it * 64;
            uint32_t d = dstS + row * ROWB + ch * 16;
            CPA16(d,          pAh + (r0 + row) * DDIM + k0);
            CPA16(d + MAT_A,  pAl + (r0 + row) * DDIM + k0);
        }
        uint32_t d2 = dstS + 2 * MAT_A + row_a * ROWB + ch * 16;
        CPA16(d2,           pBh + (c0 + row_a) * DDIM + k0);
        CPA16(d2 + MAT_Bb,  pBl + (c0 + row_a) * DDIM + k0);
        CPCOMMIT();
    };

    float acc[2][4][4];
    #pragma unroll
    for (int mt = 0; mt < 2; mt++)
        #pragma unroll
        for (int nt = 0; nt < 4; nt++)
            #pragma unroll
            for (int i = 0; i < 4; i++) acc[mt][nt][i] = 0.0f;

    load_stage(0);
    load_stage(1);

    const uint32_t aRowOff = (uint32_t)(wm * 32 + (lane & 15)) * ROWB;
    const uint32_t aColOff = (uint32_t)(((lane >> 4) & 1) << 4);
    const uint32_t bRowOff = (uint32_t)(wn * 32 + (((lane >> 4) & 1) << 3) + (lane & 7)) * ROWB;
    const uint32_t bColOff = (uint32_t)(((lane >> 3) & 1) << 4);

    for (int kt = 0; kt < DDIM / BK; kt++) {
        CPWAIT1();
        __syncthreads();
        if (kt + 2 < DDIM / BK) load_stage(kt + 2);
        const uint32_t SB = sb + (uint32_t)(kt % STG) * STG_B;
        #pragma unroll
        for (int kk = 0; kk < 2; kk++) {
            const uint32_t k16b = (uint32_t)(kk * 32);
            uint32_t ah[2][4], al[2][4], fbh[2][4], fbl[2][4];
            uint32_t aA = SB + aRowOff + k16b + aColOff;
            ldsm4(ah[0], aA);
            ldsm4(ah[1], aA + 16 * ROWB);
            ldsm4(al[0], aA + MAT_A);
            ldsm4(al[1], aA + MAT_A + 16 * ROWB);
            uint32_t bA = SB + 2 * MAT_A + bRowOff + k16b + bColOff;
            #pragma unroll
            for (int n16 = 0; n16 < 2; n16++) {
                ldsm4(fbh[n16], bA + n16 * 16 * ROWB);
                ldsm4(fbl[n16], bA + MAT_Bb + n16 * 16 * ROWB);
            }
            #pragma unroll
            for (int mt = 0; mt < 2; mt++)
                #pragma unroll
                for (int nt = 0; nt < 4; nt++) {
                    const uint32_t* bph = &fbh[nt >> 1][(nt & 1) * 2];
                    const uint32_t* bpl = &fbl[nt >> 1][(nt & 1) * 2];
                    mma16816(acc[mt][nt], ah[mt], bph[0], bph[1]);
                    mma16816(acc[mt][nt], ah[mt], bpl[0], bpl[1]);
                    mma16816(acc[mt][nt], al[mt], bph[0], bph[1]);
                }
        }
    }

    const int md = args.mode[z];
    const float sc = args.scale[z];
    #pragma unroll
    for (int mt = 0; mt < 2; mt++) {
        int row0 = r0 + wm * 32 + mt * 16 + (lane >> 2);
        #pragma unroll
        for (int nt = 0; nt < 4; nt++) {
            int col = c0 + wn * 32 + nt * 8 + (lane & 3) * 2;
            float2 bs = *(const float2*)&bias[col];
            float v0 = (acc[mt][nt][0] + bs.x) * sc;
            float v1 = (acc[mt][nt][1] + bs.y) * sc;
            float v2 = (acc[mt][nt][2] + bs.x) * sc;
            float v3 = (acc[mt][nt][3] + bs.y) * sc;
            if (md == 0) {
                float* C = args.C[z];
                *(float2*)&C[row0 * DDIM + col] = make_float2(v0, v1);
                *(float2*)&C[(row0 + 8) * DDIM + col] = make_float2(v2, v3);
            } else if (md == 1) {
                __nv_bfloat16* Oh = args.Oh[z]; __nv_bfloat16* Ol = args.Ol[z];
                int hh = col >> 6, d = col & 63;
                uint32_t u0h, u0l, u1h, u1l;
                bsplit2(v0, v1, u0h, u0l);
                bsplit2(v2, v3, u1h, u1l);
                int b0i = row0 >> 8, n0i = row0 & 255;
                size_t i0x = (size_t)(((b0i * NH + hh) * NN + n0i) * DKH + d);
                *(uint32_t*)(Oh + i0x) = u0h; *(uint32_t*)(Ol + i0x) = u0l;
                int r1i = row0 + 8;
                int b1i = r1i >> 8, n1i = r1i & 255;
                size_t i1x = (size_t)(((b1i * NH + hh) * NN + n1i) * DKH + d);
                *(uint32_t*)(Oh + i1x) = u1h; *(uint32_t*)(Ol + i1x) = u1l;
            } else {
                __nv_bfloat16* Oh = args.Oh[z]; __nv_bfloat16* Ol = args.Ol[z];
                int hh = col >> 6, d = col & 63;
                int b0i = row0 >> 8, n0i = row0 & 255;
                size_t base = (size_t)(((b0i * NH + hh) * DKH + d) * NN + n0i);
                __nv_bfloat16 h, l;
                bsplit1(v0, h, l); Oh[base] = h;           Ol[base] = l;
                bsplit1(v1, h, l); Oh[base + NN] = h;      Ol[base + NN] = l;
                bsplit1(v2, h, l); Oh[base + 8] = h;       Ol[base + 8] = l;
                bsplit1(v3, h, l); Oh[base + NN + 8] = h;  Ol[base + NN + 8] = l;
            }
        }
    }
}

// =================================================================================
// Geometry gate device body (fused trig+accumulate, f32x2 FMA)
// =================================================================================
__device__ __forceinline__ void wg_body(const float* __restrict__ box,
                                        const float* __restrict__ Wg,
                                        const float* __restrict__ bg,
                                        int wt, char* smraw)
{
    float* WgT  = (float*)smraw;                 // [64][8]
    float* bgs  = WgT + 512;                     // [8]
    float* istat = bgs + 8;                      // [6]

    const int b = wt >> 8, i = wt & 255, t = threadIdx.x;

    for (int idx = t; idx < 512; idx += 256) {
        int g = idx >> 3, h = idx & 7;
        WgT[g * 8 + h] = Wg[h * 64 + g];
    }
    if (t < 8) bgs[t] = bg[t];
    if (t == 0) {
        float4 bx = *(const float4*)&box[(b*NN + i) * 4];
        float cx = 0.5f * (bx.x + bx.z), cy = 0.5f * (bx.y + bx.w);
        float w = bx.z - bx.x + 1.0f,   h = bx.w - bx.y + 1.0f;
        istat[0] = cx; istat[1] = cy; istat[2] = w; istat[3] = h;
        istat[4] = __logf(w); istat[5] = __logf(h);
    }
    __syncthreads();

    const int j = t;
    float4 bj = *(const float4*)&box[(b*NN + j) * 4];
    float cxj = 0.5f * (bj.x + bj.z), cyj = 0.5f * (bj.y + bj.w);
    float wj = bj.z - bj.x + 1.0f,    hj = bj.w - bj.y + 1.0f;

    float ang[4];
    ang[0] = 100.0f * __logf(fmaxf(fabsf(istat[0] - cxj) / istat[2], 1e-3f));
    ang[1] = 100.0f * __logf(fmaxf(fabsf(istat[1] - cyj) / istat[3], 1e-3f));
    ang[2] = 100.0f * (istat[4] - __logf(wj));
    ang[3] = 100.0f * (istat[5] - __logf(hj));

    const float dimf[8] = {1.0f, 0.42169650342f, 0.17782794100f, 0.07498942093f,
                           0.03162277660f, 0.01333521432f, 0.00562341325f, 0.00237137371f};

    uint64_t a01 = *(const uint64_t*)&bgs[0];
    uint64_t a23 = *(const uint64_t*)&bgs[2];
    uint64_t a45 = *(const uint64_t*)&bgs[4];
    uint64_t a67 = *(const uint64_t*)&bgs[6];

    #pragma unroll
    for (int g = 0; g < 32; g++) {
        float th = ang[g >> 3] * dimf[g & 7];
        float n = rintf(th * 0.15915494309189535f);
        float r = fmaf(n, -6.283185482025146f, th);
        r = fmaf(n, 1.7484555e-7f, r);
        float s, co;
        __sincosf(r, &s, &co);
        uint64_t s2 = pack2(s), c2 = pack2(co);
        ulonglong2 wsA = *(const ulonglong2*)&WgT[g * 8];
        ulonglong2 wsB = *(const ulonglong2*)&WgT[g * 8 + 4];
        ulonglong2 wcA = *(const ulonglong2*)&WgT[(32 + g) * 8];
        ulonglong2 wcB = *(const ulonglong2*)&WgT[(32 + g) * 8 + 4];
        ffma2(a01, s2, wsA.x); ffma2(a23, s2, wsA.y);
        ffma2(a45, s2, wsB.x); ffma2(a67, s2, wsB.y);
        ffma2(a01, c2, wcA.x); ffma2(a23, c2, wcA.y);
        ffma2(a45, c2, wcB.x); ffma2(a67, c2, wcB.y);
    }

    float2 r01 = unpack2(a01), r23 = unpack2(a23);
    float2 r45 = unpack2(a45), r67 = unpack2(a67);
    float accs[8] = {r01.x, r01.y, r23.x, r23.y, r45.x, r45.y, r67.x, r67.y};
    const int base = ((b*NH) * NN + i) * NN + j;
    #pragma unroll
    for (int h = 0; h < 8; h++)
        g_wgl[base + h * (NN*NN)] = __logf(fmaxf(accs[h], 1e-6f));
}

// =================================================================================
// Fused QKV-GEMM + wg launch: 256 groups x (3 gemm + 16 wg) = 4864 blocks.
// =================================================================================
__global__ __launch_bounds__(256, 2)
void fused_qkv_wg(const GArgs args, const float* __restrict__ box,
                  const float* __restrict__ Wg, const float* __restrict__ bg)
{
    extern __shared__ char smraw[];
    const int bid = blockIdx.x;
    const int grp = bid / 19, r = bid % 19;
    if (r < 3) {
        gemm_body(args, grp * 3 + r, smraw);
    } else {
        wg_body(box, Wg, bg, grp * 16 + (r - 3), smraw);
    }
}

// O-projection: plain gemm launch (mode 0)
__global__ __launch_bounds__(256, 2)
void gemm_hmma(const GArgs args)
{
    extern __shared__ char smraw[];
    gemm_body(args, (blockIdx.y << 3) | blockIdx.x, smraw);
}

// =================================================================================
// HMMA attention (unchanged)
// =================================================================================
#define AT_KH 0
#define AT_KL 32768
#define AT_VH 65536
#define AT_VL 98304
#define AT_QH 131072
#define AT_QL 139264
#define AT_RED 147456
#define AT_PMAX (AT_RED + 4*64*68*4)
#define AT_PSUM (AT_PMAX + 1024)
#define AT_TOT  (AT_PSUM + 1024)

__global__ __launch_bounds__(256, 1)
void attn_hmma()
{
    extern __shared__ char sm[];
    const uint32_t sb = smem_u32(sm);
    const int t = threadIdx.x, lane = t & 31, wid = t >> 5;
    const int wm = wid >> 2, wn = wid & 3;
    const int bh = blockIdx.x;
    const __nv_bfloat16* kh = g_kh + (size_t)bh * NN * DKH;
    const __nv_bfloat16* kl = g_kl + (size_t)bh * NN * DKH;
    const __nv_bfloat16* vh = g_vh + (size_t)bh * DKH * NN;
    const __nv_bfloat16* vl = g_vl + (size_t)bh * DKH * NN;
    const __nv_bfloat16* qh = g_qh + (size_t)bh * NN * DKH;
    const __nv_bfloat16* ql = g_ql + (size_t)bh * NN * DKH;
    const float* wglb = g_wgl + (size_t)bh * NN * NN;

    #pragma unroll
    for (int p = 0; p < 8; p++) {
        int idx = t + p * 256; int j = idx >> 3, c = idx & 7;
        uint32_t off = ((uint32_t)(j * 128 + c * 16)) ^ ((uint32_t)(j & 7) << 4);
        CPA16(sb + AT_KH + off, kh + j * 64 + c * 8);
        CPA16(sb + AT_KL + off, kl + j * 64 + c * 8);
    }
    #pragma unroll
    for (int p = 0; p < 8; p++) {
        int idx = t + p * 256; int d = idx >> 5, c = idx & 31;
        uint32_t off = ((uint32_t)(d * 512 + c * 16)) ^ ((uint32_t)(d & 7) << 4);
        CPA16(sb + AT_VH + off, vh + d * 256 + c * 8);
        CPA16(sb + AT_VL + off, vl + d * 256 + c * 8);
    }

    const uint32_t swz = (uint32_t)(lane & 7) << 4;
    float* pmS = (float*)(sm + AT_PMAX);
    float* psS = (float*)(sm + AT_PSUM);
    float* redS = (float*)(sm + AT_RED);

    for (int it = 0; it < 4; it++) {
        const int i0 = it * 64;
        #pragma unroll
        for (int p = 0; p < 2; p++) {
            int idx = t + p * 256; int r = idx >> 3, c = idx & 7;
            uint32_t off = ((uint32_t)(r * 128 + c * 16)) ^ ((uint32_t)(r & 7) << 4);
            CPA16(sb + AT_QH + off, qh + (i0 + r) * 64 + c * 8);
            CPA16(sb + AT_QL + off, ql + (i0 + r) * 64 + c * 8);
        }
        CPCOMMIT();
        CPWAIT0();
        __syncthreads();

        float acc[2][8][4];
        #pragma unroll
        for (int mt = 0; mt < 2; mt++)
            #pragma unroll
            for (int nt = 0; nt < 8; nt++)
                #pragma unroll
                for (int u = 0; u < 4; u++) acc[mt][nt][u] = 0.0f;

        #pragma unroll
        for (int ks = 0; ks < 4; ks++) {
            uint32_t ah[2][4], al[2][4], fbh[4][4], fbl[4][4];
            uint32_t aoff = (((uint32_t)((wm * 32 + (lane & 15)) * 128
                             + ks * 32 + ((lane >> 4) & 1) * 16)) ^ swz);
            ldsm4(ah[0], sb + AT_QH + aoff);
            ldsm4(ah[1], sb + AT_QH + aoff + 2048);
            ldsm4(al[0], sb + AT_QL + aoff);
            ldsm4(al[1], sb + AT_QL + aoff + 2048);
            uint32_t boff = (((uint32_t)((wn * 64 + ((lane >> 4) & 1) * 8 + (lane & 7)) * 128
                             + ks * 32 + ((lane >> 3) & 1) * 16)) ^ swz);
            #pragma unroll
            for (int n16 = 0; n16 < 4; n16++) {
                ldsm4(fbh[n16], sb + AT_KH + boff + n16 * 2048);
                ldsm4(fbl[n16], sb + AT_KL + boff + n16 * 2048);
            }
            #pragma unroll
            for (int mt = 0; mt < 2; mt++)
                #pragma unroll
                for (int nt = 0; nt < 8; nt++) {
                    const uint32_t* bph = &fbh[nt >> 1][(nt & 1) * 2];
                    const uint32_t* bpl = &fbl[nt >> 1][(nt & 1) * 2];
                    mma16816(acc[mt][nt], ah[mt], bph[0], bph[1]);
                    mma16816(acc[mt][nt], ah[mt], bpl[0], bpl[1]);
                    mma16816(acc[mt][nt], al[mt], bph[0], bph[1]);
                }
        }

        #pragma unroll
        for (int mt = 0; mt < 2; mt++) {
            int rA = wm * 32 + mt * 16 + (lane >> 2);
            const float* w0 = wglb + (size_t)(i0 + rA) * NN + wn * 64 + (lane & 3) * 2;
            const float* w1 = w0 + 8 * NN;
            #pragma unroll
            for (int nt = 0; nt < 8; nt++) {
                float2 g0 = *(const float2*)(w0 + nt * 8);
                float2 g1 = *(const float2*)(w1 + nt * 8);
                acc[mt][nt][0] += g0.x; acc[mt][nt][1] += g0.y;
                acc[mt][nt][2] += g1.x; acc[mt][nt][3] += g1.y;
            }
        }
        float rmx[2][2];
        #pragma unroll
        for (int mt = 0; mt < 2; mt++) {
            rmx[mt][0] = -1e30f; rmx[mt][1] = -1e30f;
            #pragma unroll
            for (int nt = 0; nt < 8; nt++) {
                rmx[mt][0] = fmaxf(rmx[mt][0], fmaxf(acc[mt][nt][0], acc[mt][nt][1]));
                rmx[mt][1] = fmaxf(rmx[mt][1], fmaxf(acc[mt][nt][2], acc[mt][nt][3]));
            }
        }
        #pragma unroll
        for (int off = 1; off <= 2; off <<= 1)
            #pragma unroll
            for (int mt = 0; mt < 2; mt++) {
                rmx[mt][0] = fmaxf(rmx[mt][0], __shfl_xor_sync(~0u, rmx[mt][0], off));
                rmx[mt][1] = fmaxf(rmx[mt][1], __shfl_xor_sync(~0u, rmx[mt][1], off));
            }
        if ((lane & 3) == 0) {
            #pragma unroll
            for (int mt = 0; mt < 2; mt++) {
                int rA = wm * 32 + mt * 16 + (lane >> 2);
                pmS[wn * 64 + rA] = rmx[mt][0];
                pmS[wn * 64 + rA + 8] = rmx[mt][1];
            }
        }
        __syncthreads();

        float gm[2][2], ps[2][2];
        #pragma unroll
        for (int mt = 0; mt < 2; mt++)
            #pragma unroll
            for (int hf = 0; hf < 2; hf++) {
                int rA = wm * 32 + mt * 16 + (lane >> 2) + hf * 8;
                gm[mt][hf] = fmaxf(fmaxf(pmS[rA], pmS[64 + rA]),
                                   fmaxf(pmS[128 + rA], pmS[192 + rA]));
                ps[mt][hf] = 0.0f;
            }
        #pragma unroll
        for (int mt = 0; mt < 2; mt++)
            #pragma unroll
            for (int nt = 0; nt < 8; nt++) {
                acc[mt][nt][0] = __expf(acc[mt][nt][0] - gm[mt][0]);
                acc[mt][nt][1] = __expf(acc[mt][nt][1] - gm[mt][0]);
                acc[mt][nt][2] = __expf(acc[mt][nt][2] - gm[mt][1]);
                acc[mt][nt][3] = __expf(acc[mt][nt][3] - gm[mt][1]);
                ps[mt][0] += acc[mt][nt][0] + acc[mt][nt][1];
                ps[mt][1] += acc[mt][nt][2] + acc[mt][nt][3];
            }
        #pragma unroll
        for (int off = 1; off <= 2; off <<= 1)
            #pragma unroll
            for (int mt = 0; mt < 2; mt++) {
                ps[mt][0] += __shfl_xor_sync(~0u, ps[mt][0], off);
                ps[mt][1] += __shfl_xor_sync(~0u, ps[mt][1], off);
            }
        if ((lane & 3) == 0) {
            #pragma unroll
            for (int mt = 0; mt < 2; mt++) {
                int rA = wm * 32 + mt * 16 + (lane >> 2);
                psS[wn * 64 + rA] = ps[mt][0];
                psS[wn * 64 + rA + 8] = ps[mt][1];
            }
        }

        float pv[2][8][4];
        #pragma unroll
        for (int mt = 0; mt < 2; mt++)
            #pragma unroll
            for (int nt = 0; nt < 8; nt++)
                #pragma unroll
                for (int u = 0; u < 4; u++) pv[mt][nt][u] = 0.0f;

        #pragma unroll
        for (int kt = 0; kt < 4; kt++) {
            uint32_t aph[2][4], apl[2][4];
            #pragma unroll
            for (int mt = 0; mt < 2; mt++)
                #pragma unroll
                for (int q = 0; q < 2; q++) {
                    int nt = 2 * kt + q;
                    bsplit2(acc[mt][nt][0], acc[mt][nt][1], aph[mt][2*q], apl[mt][2*q]);
                    bsplit2(acc[mt][nt][2], acc[mt][nt][3], aph[mt][2*q+1], apl[mt][2*q+1]);
                }
            uint32_t vbh[4][4], vbl[4][4];
            uint32_t boff = (((uint32_t)((((lane >> 4) & 1) * 8 + (lane & 7)) * 512
                             + wn * 128 + kt * 32 + ((lane >> 3) & 1) * 16)) ^ swz);
            #pragma unroll
            for (int n16 = 0; n16 < 4; n16++) {
                ldsm4(vbh[n16], sb + AT_VH + boff + n16 * 8192);
                ldsm4(vbl[n16], sb + AT_VL + boff + n16 * 8192);
            }
            #pragma unroll
            for (int mt = 0; mt < 2; mt++)
                #pragma unroll
                for (int nt = 0; nt < 8; nt++) {
                    const uint32_t* bph = &vbh[nt >> 1][(nt & 1) * 2];
                    const uint32_t* bpl = &vbl[nt >> 1][(nt & 1) * 2];
                    mma16816(pv[mt][nt], aph[mt], bph[0], bph[1]);
                    mma16816(pv[mt][nt], aph[mt], bpl[0], bpl[1]);
                    mma16816(pv[mt][nt], apl[mt], bph[0], bph[1]);
                }
        }

        float* red = redS + wn * (64 * 68);
        #pragma unroll
        for (int mt = 0; mt < 2; mt++) {
            int rA = wm * 32 + mt * 16 + (lane >> 2);
            #pragma unroll
            for (int nt = 0; nt < 8; nt++) {
                int cc = nt * 8 + (lane & 3) * 2;
                *(float2*)&red[rA * 68 + cc] = make_float2(pv[mt][nt][0], pv[mt][nt][1]);
                *(float2*)&red[(rA + 8) * 68 + cc] = make_float2(pv[mt][nt][2], pv[mt][nt][3]);
            }
        }
        __syncthreads();

        {
            int row = t >> 2, cg = (t & 3) * 16;
            float inv = 1.0f / (psS[row] + psS[64 + row] + psS[128 + row] + psS[192 + row]);
            float vsum[16];
            #pragma unroll
            for (int u4 = 0; u4 < 4; u4++) {
                float4 x = *(float4*)&redS[row * 68 + cg + u4 * 4];
                #pragma unroll
                for (int s = 1; s < 4; s++) {
                    float4 y = *(float4*)&redS[s * (64*68) + row * 68 + cg + u4 * 4];
                    x.x += y.x; x.y += y.y; x.z += y.z; x.w += y.w;
                }
                vsum[u4*4+0] = x.x * inv; vsum[u4*4+1] = x.y * inv;
                vsum[u4*4+2] = x.z * inv; vsum[u4*4+3] = x.w * inv;
            }
            uint32_t hi[8], lo[8];
            #pragma unroll
            for (int u = 0; u < 8; u++)
                bsplit2(vsum[2*u], vsum[2*u+1], hi[u], lo[u]);
            int orow = (bh >> 3) * NN + i0 + row;
            int ocol = (bh & 7) * DKH + cg;
            __nv_bfloat16* oh = g_ah + (size_t)orow * DDIM + ocol;
            __nv_bfloat16* ol = g_al + (size_t)orow * DDIM + ocol;
            *(uint4*)oh       = make_uint4(hi[0], hi[1], hi[2], hi[3]);
            *(uint4*)(oh + 8) = make_uint4(hi[4], hi[5], hi[6], hi[7]);
            *(uint4*)ol       = make_uint4(lo[0], lo[1], lo[2], lo[3]);
            *(uint4*)(ol + 8) = make_uint4(lo[4], lo[5], lo[6], lo[7]);
        }
    }
}

// =================================================================================
// launch
// =================================================================================
extern "C" void kernel_launch(void* const* d_in, const int* in_sizes, int n_in,
                              void* d_out, int out_size)
{
    const float* query = (const float*)d_in[0];
    const float* key   = (const float*)d_in[1];
    const float* value = (const float*)d_in[2];
    const float* box   = (const float*)d_in[3];
    const float* Wq = (const float*)d_in[4];
    const float* bq = (const float*)d_in[5];
    const float* Wk = (const float*)d_in[6];
    const float* bk = (const float*)d_in[7];
    const float* Wv = (const float*)d_in[8];
    const float* bv = (const float*)d_in[9];
    const float* Wo = (const float*)d_in[10];
    const float* bo = (const float*)d_in[11];
    const float* Wg = (const float*)d_in[12];
    const float* bg = (const float*)d_in[13];
    float* out = (float*)d_out;

    __nv_bfloat16 *pah, *pal, *pwh, *pwl, *pqh, *pql, *pkh, *pkl, *pvh, *pvl;
    cudaGetSymbolAddress((void**)&pah, g_ah);
    cudaGetSymbolAddress((void**)&pal, g_al);
    cudaGetSymbolAddress((void**)&pwh, g_wTh);
    cudaGetSymbolAddress((void**)&pwl, g_wTl);
    cudaGetSymbolAddress((void**)&pqh, g_qh);
    cudaGetSymbolAddress((void**)&pql, g_ql);
    cudaGetSymbolAddress((void**)&pkh, g_kh);
    cudaGetSymbolAddress((void**)&pkl, g_kl);
    cudaGetSymbolAddress((void**)&pvh, g_vh);
    cudaGetSymbolAddress((void**)&pvl, g_vl);

    static bool attr_set = false;
    if (!attr_set) {
        cudaFuncSetAttribute(fused_qkv_wg, cudaFuncAttributeMaxDynamicSharedMemorySize, GDYN);
        cudaFuncSetAttribute(gemm_hmma, cudaFuncAttributeMaxDynamicSharedMemorySize, GDYN);
        cudaFuncSetAttribute(attn_hmma, cudaFuncAttributeMaxDynamicSharedMemorySize, AT_TOT);
        attr_set = true;
    }

    wconv_kernel<<<dim3(16, 16, 4), dim3(32, 8)>>>(Wq, Wk, Wv, Wo);
    asplit3_kernel<<<dim3(MROWS * DDIM / 4 / 256, 3), 256>>>(query, key, value);

    GArgs ga;
    ga.Ah = pah; ga.Al = pal; ga.Bh = pwh; ga.Bl = pwl;
    ga.bias[0] = bq; ga.bias[1] = bk; ga.bias[2] = bv;
    ga.C[0] = ga.C[1] = ga.C[2] = nullptr;
    ga.Oh[0] = pqh; ga.Ol[0] = pql;
    ga.Oh[1] = pkh; ga.Ol[1] = pkl;
    ga.Oh[2] = pvh; ga.Ol[2] = pvl;
    ga.scale[0] = 0.125f; ga.scale[1] = 1.0f; ga.scale[2] = 1.0f;
    ga.mode[0] = 1; ga.mode[1] = 1; ga.mode[2] = 2;

    // fused: QKV projections + geometry gate in one launch (interleaved roles)
    fused_qkv_wg<<<4864, 256, GDYN>>>(ga, box, Wg, bg);

    attn_hmma<<<NB * NH, 256, AT_TOT>>>();

    GArgs go;
    go.Ah = pah; go.Al = pal;
    go.Bh = pwh + 3 * DDIM * DDIM; go.Bl = pwl + 3 * DDIM * DDIM;
    go.bias[0] = go.bias[1] = go.bias[2] = bo;
    go.C[0] = go.C[1] = go.C[2] = out;
    go.Oh[0] = go.Oh[1] = go.Oh[2] = nullptr;
    go.Ol[0] = go.Ol[1] = go.Ol[2] = nullptr;
    go.scale[0] = go.scale[1] = go.scale[2] = 1.0f;
    go.mode[0] = go.mode[1] = go.mode[2] = 0;
    gemm_hmma<<<dim3(8, 32, 1), 256, GDYN>>>(go);
}

// round 12
// speedup vs baseline: 1.1198x; 1.1198x over previous
#include <cuda_runtime.h>
#include <cuda_bf16.h>
#include <math.h>
#include <stdint.h>

#define NB 16
#define NN 256
#define DDIM 512
#define NH 8
#define DKH 64
#define MROWS (NB*NN)        // 4096

// ---------------- scratch ----------------
__device__ float g_wgl[NB*NH*NN*NN];
__device__ __nv_bfloat16 g_wTh[4*DDIM*DDIM];
__device__ __nv_bfloat16 g_wTl[4*DDIM*DDIM];
__device__ __nv_bfloat16 g_ah[3*MROWS*DDIM];
__device__ __nv_bfloat16 g_al[3*MROWS*DDIM];
__device__ __nv_bfloat16 g_qh[NB*NH*NN*DKH], g_ql[NB*NH*NN*DKH];
__device__ __nv_bfloat16 g_kh[NB*NH*NN*DKH], g_kl[NB*NH*NN*DKH];
__device__ __nv_bfloat16 g_vh[NB*NH*DKH*NN], g_vl[NB*NH*DKH*NN];

// =========================== helpers ================================
__device__ __forceinline__ uint32_t smem_u32(const void* p) {
    uint32_t a;
    asm("{ .reg .u64 t; cvta.to.shared.u64 t, %1; cvt.u32.u64 %0, t; }" : "=r"(a) : "l"(p));
    return a;
}
__device__ __forceinline__ void ldsm4(uint32_t* r, uint32_t addr) {
    asm volatile("ldmatrix.sync.aligned.m8n8.x4.shared.b16 {%0,%1,%2,%3}, [%4];"
                 : "=r"(r[0]), "=r"(r[1]), "=r"(r[2]), "=r"(r[3]) : "r"(addr));
}
__device__ __forceinline__ void mma16816(float* d, const uint32_t* a, uint32_t b0, uint32_t b1) {
    asm volatile("mma.sync.aligned.m16n8k16.row.col.f32.bf16.bf16.f32 "
                 "{%0,%1,%2,%3}, {%4,%5,%6,%7}, {%8,%9}, {%0,%1,%2,%3};"
                 : "+f"(d[0]), "+f"(d[1]), "+f"(d[2]), "+f"(d[3])
                 : "r"(a[0]), "r"(a[1]), "r"(a[2]), "r"(a[3]), "r"(b0), "r"(b1));
}
#define CPA16(dst, src) \
    asm volatile("cp.async.cg.shared.global [%0], [%1], 16;" :: "r"(dst), "l"(src) : "memory")
#define CPCOMMIT() asm volatile("cp.async.commit_group;" ::: "memory")
#define CPWAIT1()  asm volatile("cp.async.wait_group 1;" ::: "memory")
#define CPWAIT0()  asm volatile("cp.async.wait_group 0;" ::: "memory")

__device__ __forceinline__ void bsplit2(float x, float y, uint32_t& h, uint32_t& l) {
    __nv_bfloat162 hh = __floats2bfloat162_rn(x, y);
    float2 r = __bfloat1622float2(hh);
    __nv_bfloat162 ll = __floats2bfloat162_rn(x - r.x, y - r.y);
    h = *(uint32_t*)&hh; l = *(uint32_t*)&ll;
}
__device__ __forceinline__ void bsplit1(float x, __nv_bfloat16& h, __nv_bfloat16& l) {
    h = __float2bfloat16_rn(x);
    l = __float2bfloat16_rn(x - __bfloat162float(h));
}
__device__ __forceinline__ void ffma2(uint64_t& acc, uint64_t a, uint64_t b) {
    asm("fma.rn.f32x2 %0, %1, %2, %0;" : "+l"(acc) : "l"(a), "l"(b));
}
__device__ __forceinline__ uint64_t pack2(float x) {
    uint64_t r; asm("mov.b64 %0, {%1, %1};" : "=l"(r) : "f"(x)); return r;
}
__device__ __forceinline__ float2 unpack2(uint64_t v) {
    float2 f; asm("mov.b64 {%0, %1}, %2;" : "=f"(f.x), "=f"(f.y) : "l"(v)); return f;
}

// =================================================================================
// Weight transpose + bf16 split
// =================================================================================
__global__ __launch_bounds__(256)
void wconv_kernel(const float* __restrict__ w0, const float* __restrict__ w1,
                  const float* __restrict__ w2, const float* __restrict__ w3)
{
    __shared__ float tile[32][33];
    const float* W = (blockIdx.z == 0) ? w0 : (blockIdx.z == 1) ? w1 :
                     (blockIdx.z == 2) ? w2 : w3;
    __nv_bfloat16* Th = g_wTh + blockIdx.z * (DDIM * DDIM);
    __nv_bfloat16* Tl = g_wTl + blockIdx.z * (DDIM * DDIM);
    const int x0 = blockIdx.x * 32, y0 = blockIdx.y * 32;
    const int tx = threadIdx.x;
    #pragma unroll
    for (int r = threadIdx.y; r < 32; r += 8)
        tile[r][tx] = W[(y0 + r) * DDIM + x0 + tx];
    __syncthreads();
    #pragma unroll
    for (int r = threadIdx.y; r < 32; r += 8) {
        float v = tile[tx][r];
        __nv_bfloat16 h, l; bsplit1(v, h, l);
        Th[(x0 + r) * DDIM + y0 + tx] = h;
        Tl[(x0 + r) * DDIM + y0 + tx] = l;
    }
}

// =================================================================================
// Input split
// =================================================================================
__global__ __launch_bounds__(256)
void asplit3_kernel(const float* __restrict__ q, const float* __restrict__ k,
                    const float* __restrict__ v)
{
    const int z = blockIdx.y;
    const float* src = (z == 0) ? q : (z == 1) ? k : v;
    __nv_bfloat16* oh = g_ah + z * (MROWS * DDIM);
    __nv_bfloat16* ol = g_al + z * (MROWS * DDIM);
    const int i4 = blockIdx.x * 256 + threadIdx.x;
    float4 f = ((const float4*)src)[i4];
    uint32_t h0, l0, h1, l1;
    bsplit2(f.x, f.y, h0, l0);
    bsplit2(f.z, f.w, h1, l1);
    ((uint2*)oh)[i4] = make_uint2(h0, h1);
    ((uint2*)ol)[i4] = make_uint2(l0, l1);
}

// =================================================================================
// HMMA GEMM (bf16 split, 3 passes). BM=128, BN=64, BK=32, 3-stage, 2 CTAs/SM.
// =================================================================================
#define BK 32
#define STG 3
#define ROWB 80
#define MAT_A (128*ROWB)
#define MAT_Bb (64*ROWB)
#define STG_B (2*MAT_A + 2*MAT_Bb)
#define GDYN (STG*STG_B)

struct GArgs {
    const __nv_bfloat16 *Ah, *Al, *Bh, *Bl;
    const float* bias[3];
    float*       C[3];
    __nv_bfloat16 *Oh[3], *Ol[3];
    float scale[3];
    int mode[3];
};

__global__ __launch_bounds__(256, 2)
void gemm_hmma(const GArgs args)
{
    extern __shared__ char smraw[];
    const uint32_t sb = smem_u32(smraw);
    const int t = threadIdx.x, lane = t & 31, wid = t >> 5;
    const int wm = wid & 3, wn = wid >> 2;
    const int z = blockIdx.z;
    const int r0 = blockIdx.y * 128, c0 = blockIdx.x * 64;

    const __nv_bfloat16* pAh = args.Ah + (size_t)z * MROWS * DDIM;
    const __nv_bfloat16* pAl = args.Al + (size_t)z * MROWS * DDIM;
    const __nv_bfloat16* pBh = args.Bh + (size_t)z * DDIM * DDIM;
    const __nv_bfloat16* pBl = args.Bl + (size_t)z * DDIM * DDIM;
    const float* bias = args.bias[z];

    const int row_a = t >> 2, ch = t & 3;
    auto load_stage = [&](int kt) {
        uint32_t dstS = sb + (uint32_t)(kt % STG) * STG_B;
        int k0 = kt * BK + ch * 8;
        #pragma unroll
        for (int it = 0; it < 2; it++) {
            int row = row_a + it * 64;
            uint32_t d = dstS + row * ROWB + ch * 16;
            CPA16(d,          pAh + (r0 + row) * DDIM + k0);
            CPA16(d + MAT_A,  pAl + (r0 + row) * DDIM + k0);
        }
        uint32_t d2 = dstS + 2 * MAT_A + row_a * ROWB + ch * 16;
        CPA16(d2,           pBh + (c0 + row_a) * DDIM + k0);
        CPA16(d2 + MAT_Bb,  pBl + (c0 + row_a) * DDIM + k0);
        CPCOMMIT();
    };

    float acc[2][4][4];
    #pragma unroll
    for (int mt = 0; mt < 2; mt++)
        #pragma unroll
        for (int nt = 0; nt < 4; nt++)
            #pragma unroll
            for (int i = 0; i < 4; i++) acc[mt][nt][i] = 0.0f;

    load_stage(0);
    load_stage(1);

    const uint32_t aRowOff = (uint32_t)(wm * 32 + (lane & 15)) * ROWB;
    const uint32_t aColOff = (uint32_t)(((lane >> 4) & 1) << 4);
    const uint32_t bRowOff = (uint32_t)(wn * 32 + (((lane >> 4) & 1) << 3) + (lane & 7)) * ROWB;
    const uint32_t bColOff = (uint32_t)(((lane >> 3) & 1) << 4);

    for (int kt = 0; kt < DDIM / BK; kt++) {
        CPWAIT1();
        __syncthreads();
        if (kt + 2 < DDIM / BK) load_stage(kt + 2);
        const uint32_t SB = sb + (uint32_t)(kt % STG) * STG_B;
        #pragma unroll
        for (int kk = 0; kk < 2; kk++) {
            const uint32_t k16b = (uint32_t)(kk * 32);
            uint32_t ah[2][4], al[2][4], fbh[2][4], fbl[2][4];
            uint32_t aA = SB + aRowOff + k16b + aColOff;
            ldsm4(ah[0], aA);
            ldsm4(ah[1], aA + 16 * ROWB);
            ldsm4(al[0], aA + MAT_A);
            ldsm4(al[1], aA + MAT_A + 16 * ROWB);
            uint32_t bA = SB + 2 * MAT_A + bRowOff + k16b + bColOff;
            #pragma unroll
            for (int n16 = 0; n16 < 2; n16++) {
                ldsm4(fbh[n16], bA + n16 * 16 * ROWB);
                ldsm4(fbl[n16], bA + MAT_Bb + n16 * 16 * ROWB);
            }
            #pragma unroll
            for (int mt = 0; mt < 2; mt++)
                #pragma unroll
                for (int nt = 0; nt < 4; nt++) {
                    const uint32_t* bph = &fbh[nt >> 1][(nt & 1) * 2];
                    const uint32_t* bpl = &fbl[nt >> 1][(nt & 1) * 2];
                    mma16816(acc[mt][nt], ah[mt], bph[0], bph[1]);
                    mma16816(acc[mt][nt], ah[mt], bpl[0], bpl[1]);
                    mma16816(acc[mt][nt], al[mt], bph[0], bph[1]);
                }
        }
    }

    const int md = args.mode[z];
    const float sc = args.scale[z];
    #pragma unroll
    for (int mt = 0; mt < 2; mt++) {
        int row0 = r0 + wm * 32 + mt * 16 + (lane >> 2);
        #pragma unroll
        for (int nt = 0; nt < 4; nt++) {
            int col = c0 + wn * 32 + nt * 8 + (lane & 3) * 2;
            float2 bs = *(const float2*)&bias[col];
            float v0 = (acc[mt][nt][0] + bs.x) * sc;
            float v1 = (acc[mt][nt][1] + bs.y) * sc;
            float v2 = (acc[mt][nt][2] + bs.x) * sc;
            float v3 = (acc[mt][nt][3] + bs.y) * sc;
            if (md == 0) {
                float* C = args.C[z];
                *(float2*)&C[row0 * DDIM + col] = make_float2(v0, v1);
                *(float2*)&C[(row0 + 8) * DDIM + col] = make_float2(v2, v3);
            } else if (md == 1) {
                __nv_bfloat16* Oh = args.Oh[z]; __nv_bfloat16* Ol = args.Ol[z];
                int hh = col >> 6, d = col & 63;
                uint32_t u0h, u0l, u1h, u1l;
                bsplit2(v0, v1, u0h, u0l);
                bsplit2(v2, v3, u1h, u1l);
                int b0i = row0 >> 8, n0i = row0 & 255;
                size_t i0x = (size_t)(((b0i * NH + hh) * NN + n0i) * DKH + d);
                *(uint32_t*)(Oh + i0x) = u0h; *(uint32_t*)(Ol + i0x) = u0l;
                int r1i = row0 + 8;
                int b1i = r1i >> 8, n1i = r1i & 255;
                size_t i1x = (size_t)(((b1i * NH + hh) * NN + n1i) * DKH + d);
                *(uint32_t*)(Oh + i1x) = u1h; *(uint32_t*)(Ol + i1x) = u1l;
            } else {
                __nv_bfloat16* Oh = args.Oh[z]; __nv_bfloat16* Ol = args.Ol[z];
                int hh = col >> 6, d = col & 63;
                int b0i = row0 >> 8, n0i = row0 & 255;
                size_t base = (size_t)(((b0i * NH + hh) * DKH + d) * NN + n0i);
                __nv_bfloat16 h, l;
                bsplit1(v0, h, l); Oh[base] = h;           Ol[base] = l;
                bsplit1(v1, h, l); Oh[base + NN] = h;      Ol[base + NN] = l;
                bsplit1(v2, h, l); Oh[base + 8] = h;       Ol[base + 8] = l;
                bsplit1(v3, h, l); Oh[base + NN + 8] = h;  Ol[base + NN + 8] = l;
            }
        }
    }
}

// =================================================================================
// Geometry gate (R8 version)
// =================================================================================
__global__ __launch_bounds__(256)
void wg_kernel(const float* __restrict__ box, const float* __restrict__ Wg,
               const float* __restrict__ bg)
{
    __shared__ __align__(16) float WgT[64][8];
    __shared__ __align__(16) float bgs[8];
    __shared__ float istat[6];

    const int b = blockIdx.y, i = blockIdx.x, t = threadIdx.x;

    for (int idx = t; idx < 512; idx += 256) {
        int g = idx >> 3, h = idx & 7;
        WgT[g][h] = Wg[h * 64 + g];
    }
    if (t < 8) bgs[t] = bg[t];
    if (t == 0) {
        float4 bx = *(const float4*)&box[(b*NN + i) * 4];
        float cx = 0.5f * (bx.x + bx.z), cy = 0.5f * (bx.y + bx.w);
        float w = bx.z - bx.x + 1.0f,   h = bx.w - bx.y + 1.0f;
        istat[0] = cx; istat[1] = cy; istat[2] = w; istat[3] = h;
        istat[4] = __logf(w); istat[5] = __logf(h);
    }
    __syncthreads();

    const int j = t;
    float4 bj = *(const float4*)&box[(b*NN + j) * 4];
    float cxj = 0.5f * (bj.x + bj.z), cyj = 0.5f * (bj.y + bj.w);
    float wj = bj.z - bj.x + 1.0f,    hj = bj.w - bj.y + 1.0f;

    float ang[4];
    ang[0] = 100.0f * __logf(fmaxf(fabsf(istat[0] - cxj) / istat[2], 1e-3f));
    ang[1] = 100.0f * __logf(fmaxf(fabsf(istat[1] - cyj) / istat[3], 1e-3f));
    ang[2] = 100.0f * (istat[4] - __logf(wj));
    ang[3] = 100.0f * (istat[5] - __logf(hj));

    const float dimf[8] = {1.0f, 0.42169650342f, 0.17782794100f, 0.07498942093f,
                           0.03162277660f, 0.01333521432f, 0.00562341325f, 0.00237137371f};

    uint64_t a01 = *(const uint64_t*)&bgs[0];
    uint64_t a23 = *(const uint64_t*)&bgs[2];
    uint64_t a45 = *(const uint64_t*)&bgs[4];
    uint64_t a67 = *(const uint64_t*)&bgs[6];

    #pragma unroll
    for (int g = 0; g < 32; g++) {
        float th = ang[g >> 3] * dimf[g & 7];
        float n = rintf(th * 0.15915494309189535f);
        float r = fmaf(n, -6.283185482025146f, th);
        r = fmaf(n, 1.7484555e-7f, r);
        float s, co;
        __sincosf(r, &s, &co);
        uint64_t s2 = pack2(s), c2 = pack2(co);
        ulonglong2 wsA = *(const ulonglong2*)&WgT[g][0];
        ulonglong2 wsB = *(const ulonglong2*)&WgT[g][4];
        ulonglong2 wcA = *(const ulonglong2*)&WgT[32 + g][0];
        ulonglong2 wcB = *(const ulonglong2*)&WgT[32 + g][4];
        ffma2(a01, s2, wsA.x); ffma2(a23, s2, wsA.y);
        ffma2(a45, s2, wsB.x); ffma2(a67, s2, wsB.y);
        ffma2(a01, c2, wcA.x); ffma2(a23, c2, wcA.y);
        ffma2(a45, c2, wcB.x); ffma2(a67, c2, wcB.y);
    }

    float2 r01 = unpack2(a01), r23 = unpack2(a23);
    float2 r45 = unpack2(a45), r67 = unpack2(a67);
    float accs[8] = {r01.x, r01.y, r23.x, r23.y, r45.x, r45.y, r67.x, r67.y};
    const int base = ((b*NH) * NN + i) * NN + j;
    #pragma unroll
    for (int h = 0; h < 8; h++)
        g_wgl[base + h * (NN*NN)] = __logf(fmaxf(accs[h], 1e-6f));
}

// =================================================================================
// Flash attention: CTA = (b,h,q-half). 256 threads, 8 warps x m16 rows.
// Q (128x64 split) resident; K/V streamed in 64-j tiles, 2-stage cp.async.
// Online softmax in registers; PV accumulates in registers (no split-K).
// smem: QH 16K | QL 16K | 2 x [KH 8K | KL 8K | VH 8K | VL 8K] = 96K -> occ 2.
// =================================================================================
#define AF_QH 0
#define AF_QL 16384
#define AF_KV 32768
#define AF_STAGE 32768
#define AF_TOT (AF_KV + 2*AF_STAGE)   // 98304

__global__ __launch_bounds__(256, 2)
void attn_flash()
{
    extern __shared__ char sm[];
    const uint32_t sb = smem_u32(sm);
    const int t = threadIdx.x, lane = t & 31, w = t >> 5;
    const int bh = blockIdx.x >> 1, half = blockIdx.x & 1;
    const __nv_bfloat16* kh = g_kh + (size_t)bh * NN * DKH;
    const __nv_bfloat16* kl = g_kl + (size_t)bh * NN * DKH;
    const __nv_bfloat16* vh = g_vh + (size_t)bh * DKH * NN;
    const __nv_bfloat16* vl = g_vl + (size_t)bh * DKH * NN;
    const __nv_bfloat16* qh = g_qh + (size_t)bh * NN * DKH + (size_t)half * 128 * DKH;
    const __nv_bfloat16* ql = g_ql + (size_t)bh * NN * DKH + (size_t)half * 128 * DKH;
    const float* wglb = g_wgl + (size_t)bh * NN * NN + (size_t)(half * 128) * NN;

    // Q: 128 rows x 128B, hi+lo (1024 chunk-tasks each)
    #pragma unroll
    for (int p = 0; p < 4; p++) {
        int idx = t + p * 256; int r = idx >> 3, c = idx & 7;
        uint32_t off = ((uint32_t)(r * 128 + c * 16)) ^ ((uint32_t)(r & 7) << 4);
        CPA16(sb + AF_QH + off, qh + r * 64 + c * 8);
        CPA16(sb + AF_QL + off, ql + r * 64 + c * 8);
    }
    auto load_kv = [&](int kt) {
        int j0 = kt * 64;
        uint32_t dst = sb + AF_KV + (uint32_t)(kt & 1) * AF_STAGE;
        #pragma unroll
        for (int p = 0; p < 2; p++) {
            int idx = t + p * 256; int r = idx >> 3, c = idx & 7;
            uint32_t off = ((uint32_t)(r * 128 + c * 16)) ^ ((uint32_t)(r & 7) << 4);
            CPA16(dst + off,          kh + (j0 + r) * 64 + c * 8);
            CPA16(dst + 8192 + off,   kl + (j0 + r) * 64 + c * 8);
            CPA16(dst + 16384 + off,  vh + r * 256 + j0 + c * 8);
            CPA16(dst + 24576 + off,  vl + r * 256 + j0 + c * 8);
        }
        CPCOMMIT();
    };
    load_kv(0);   // group 0 (includes Q loads)
    load_kv(1);   // group 1

    const uint32_t swz = (uint32_t)(lane & 7) << 4;
    const uint32_t aoffBase = (uint32_t)((w * 16 + (lane & 15)) * 128 + ((lane >> 4) & 1) * 16);
    const uint32_t boffBase = (uint32_t)(((((lane >> 4) & 1) * 8) + (lane & 7)) * 128 + ((lane >> 3) & 1) * 16);

    float mprev0 = -1e30f, mprev1 = -1e30f;
    float ssum0 = 0.0f, ssum1 = 0.0f;
    float oacc[8][4];
    #pragma unroll
    for (int nt = 0; nt < 8; nt++)
        #pragma unroll
        for (int u = 0; u < 4; u++) oacc[nt][u] = 0.0f;

    #pragma unroll
    for (int kt = 0; kt < 4; kt++) {
        if (kt == 3) { CPWAIT0(); } else { CPWAIT1(); }
        __syncthreads();
        const uint32_t KB = sb + AF_KV + (uint32_t)(kt & 1) * AF_STAGE;

        // ---- S = Q K^T for this j-tile (16 x 64 per warp) ----
        float acc[8][4];
        #pragma unroll
        for (int nt = 0; nt < 8; nt++)
            #pragma unroll
            for (int u = 0; u < 4; u++) acc[nt][u] = 0.0f;

        #pragma unroll
        for (int ks = 0; ks < 4; ks++) {
            uint32_t ah[4], al[4];
            uint32_t aA = (aoffBase + (uint32_t)(ks * 32)) ^ swz;
            ldsm4(ah, sb + AF_QH + aA);
            ldsm4(al, sb + AF_QL + aA);
            uint32_t bA = (boffBase + (uint32_t)(ks * 32)) ^ swz;
            #pragma unroll
            for (int n16 = 0; n16 < 4; n16++) {
                uint32_t fbh[4], fbl[4];
                ldsm4(fbh, KB + bA + n16 * 2048);
                ldsm4(fbl, KB + 8192 + bA + n16 * 2048);
                #pragma unroll
                for (int q = 0; q < 2; q++) {
                    int nt = n16 * 2 + q;
                    mma16816(acc[nt], ah, fbh[q*2], fbh[q*2+1]);
                    mma16816(acc[nt], ah, fbl[q*2], fbl[q*2+1]);
                    mma16816(acc[nt], al, fbh[q*2], fbh[q*2+1]);
                }
            }
        }

        // ---- + wgl ----
        {
            int rA = w * 16 + (lane >> 2);
            const float* w0p = wglb + (size_t)rA * NN + kt * 64 + (lane & 3) * 2;
            const float* w1p = w0p + 8 * NN;
            #pragma unroll
            for (int nt = 0; nt < 8; nt++) {
                float2 g0 = *(const float2*)(w0p + nt * 8);
                float2 g1 = *(const float2*)(w1p + nt * 8);
                acc[nt][0] += g0.x; acc[nt][1] += g0.y;
                acc[nt][2] += g1.x; acc[nt][3] += g1.y;
            }
        }

        // ---- online softmax (rows fully in-warp; quad shuffles) ----
        float mt0 = -1e30f, mt1 = -1e30f;
        #pragma unroll
        for (int nt = 0; nt < 8; nt++) {
            mt0 = fmaxf(mt0, fmaxf(acc[nt][0], acc[nt][1]));
            mt1 = fmaxf(mt1, fmaxf(acc[nt][2], acc[nt][3]));
        }
        #pragma unroll
        for (int off = 1; off <= 2; off <<= 1) {
            mt0 = fmaxf(mt0, __shfl_xor_sync(~0u, mt0, off));
            mt1 = fmaxf(mt1, __shfl_xor_sync(~0u, mt1, off));
        }
        float mn0 = fmaxf(mprev0, mt0), mn1 = fmaxf(mprev1, mt1);
        float f0 = __expf(mprev0 - mn0), f1 = __expf(mprev1 - mn1);
        mprev0 = mn0; mprev1 = mn1;
        float ls0 = 0.0f, ls1 = 0.0f;
        #pragma unroll
        for (int nt = 0; nt < 8; nt++) {
            acc[nt][0] = __expf(acc[nt][0] - mn0);
            acc[nt][1] = __expf(acc[nt][1] - mn0);
            acc[nt][2] = __expf(acc[nt][2] - mn1);
            acc[nt][3] = __expf(acc[nt][3] - mn1);
            ls0 += acc[nt][0] + acc[nt][1];
            ls1 += acc[nt][2] + acc[nt][3];
            oacc[nt][0] *= f0; oacc[nt][1] *= f0;
            oacc[nt][2] *= f1; oacc[nt][3] *= f1;
        }
        #pragma unroll
        for (int off = 1; off <= 2; off <<= 1) {
            ls0 += __shfl_xor_sync(~0u, ls0, off);
            ls1 += __shfl_xor_sync(~0u, ls1, off);
        }
        ssum0 = ssum0 * f0 + ls0;
        ssum1 = ssum1 * f1 + ls1;

        // ---- PV accumulate: O += P @ Vtile (K = 64 j) ----
        #pragma unroll
        for (int kt2 = 0; kt2 < 4; kt2++) {
            uint32_t aph[4], apl[4];
            bsplit2(acc[2*kt2][0],   acc[2*kt2][1],   aph[0], apl[0]);
            bsplit2(acc[2*kt2][2],   acc[2*kt2][3],   aph[1], apl[1]);
            bsplit2(acc[2*kt2+1][0], acc[2*kt2+1][1], aph[2], apl[2]);
            bsplit2(acc[2*kt2+1][2], acc[2*kt2+1][3], aph[3], apl[3]);
            uint32_t bA = (boffBase + (uint32_t)(kt2 * 32)) ^ swz;
            #pragma unroll
            for (int n16 = 0; n16 < 4; n16++) {
                uint32_t vbh[4], vbl[4];
                ldsm4(vbh, KB + 16384 + bA + n16 * 2048);
                ldsm4(vbl, KB + 24576 + bA + n16 * 2048);
                #pragma unroll
                for (int q = 0; q < 2; q++) {
                    int nt = n16 * 2 + q;
                    mma16816(oacc[nt], aph, vbh[q*2], vbh[q*2+1]);
                    mma16816(oacc[nt], aph, vbl[q*2], vbl[q*2+1]);
                    mma16816(oacc[nt], apl, vbh[q*2], vbh[q*2+1]);
                }
            }
        }
        __syncthreads();
        if (kt < 2) load_kv(kt + 2);
    }

    // ---- normalize + split-bf16 out to g_ah/g_al slot 0 ----
    {
        float inv0 = 1.0f / ssum0, inv1 = 1.0f / ssum1;
        int rA = w * 16 + (lane >> 2);
        int orow = (bh >> 3) * NN + half * 128 + rA;
        int ocol = (bh & 7) * DKH + (lane & 3) * 2;
        #pragma unroll
        for (int nt = 0; nt < 8; nt++) {
            float v0 = oacc[nt][0] * inv0, v1 = oacc[nt][1] * inv0;
            float v2 = oacc[nt][2] * inv1, v3 = oacc[nt][3] * inv1;
            uint32_t h0, l0, h1, l1;
            bsplit2(v0, v1, h0, l0);
            bsplit2(v2, v3, h1, l1);
            size_t i0x = (size_t)orow * DDIM + ocol + nt * 8;
            size_t i1x = (size_t)(orow + 8) * DDIM + ocol + nt * 8;
            *(uint32_t*)(g_ah + i0x) = h0; *(uint32_t*)(g_al + i0x) = l0;
            *(uint32_t*)(g_ah + i1x) = h1; *(uint32_t*)(g_al + i1x) = l1;
        }
    }
}

// =================================================================================
// launch — R8 schedule with attn_flash
// =================================================================================
extern "C" void kernel_launch(void* const* d_in, const int* in_sizes, int n_in,
                              void* d_out, int out_size)
{
    const float* query = (const float*)d_in[0];
    const float* key   = (const float*)d_in[1];
    const float* value = (const float*)d_in[2];
    const float* box   = (const float*)d_in[3];
    const float* Wq = (const float*)d_in[4];
    const float* bq = (const float*)d_in[5];
    const float* Wk = (const float*)d_in[6];
    const float* bk = (const float*)d_in[7];
    const float* Wv = (const float*)d_in[8];
    const float* bv = (const float*)d_in[9];
    const float* Wo = (const float*)d_in[10];
    const float* bo = (const float*)d_in[11];
    const float* Wg = (const float*)d_in[12];
    const float* bg = (const float*)d_in[13];
    float* out = (float*)d_out;

    __nv_bfloat16 *pah, *pal, *pwh, *pwl, *pqh, *pql, *pkh, *pkl, *pvh, *pvl;
    cudaGetSymbolAddress((void**)&pah, g_ah);
    cudaGetSymbolAddress((void**)&pal, g_al);
    cudaGetSymbolAddress((void**)&pwh, g_wTh);
    cudaGetSymbolAddress((void**)&pwl, g_wTl);
    cudaGetSymbolAddress((void**)&pqh, g_qh);
    cudaGetSymbolAddress((void**)&pql, g_ql);
    cudaGetSymbolAddress((void**)&pkh, g_kh);
    cudaGetSymbolAddress((void**)&pkl, g_kl);
    cudaGetSymbolAddress((void**)&pvh, g_vh);
    cudaGetSymbolAddress((void**)&pvl, g_vl);

    static bool attr_set = false;
    if (!attr_set) {
        cudaFuncSetAttribute(gemm_hmma, cudaFuncAttributeMaxDynamicSharedMemorySize, GDYN);
        cudaFuncSetAttribute(attn_flash, cudaFuncAttributeMaxDynamicSharedMemorySize, AF_TOT);
        attr_set = true;
    }

    wconv_kernel<<<dim3(16, 16, 4), dim3(32, 8)>>>(Wq, Wk, Wv, Wo);
    asplit3_kernel<<<dim3(MROWS * DDIM / 4 / 256, 3), 256>>>(query, key, value);

    GArgs ga;
    ga.Ah = pah; ga.Al = pal; ga.Bh = pwh; ga.Bl = pwl;
    ga.bias[0] = bq; ga.bias[1] = bk; ga.bias[2] = bv;
    ga.C[0] = ga.C[1] = ga.C[2] = nullptr;
    ga.Oh[0] = pqh; ga.Ol[0] = pql;
    ga.Oh[1] = pkh; ga.Ol[1] = pkl;
    ga.Oh[2] = pvh; ga.Ol[2] = pvl;
    ga.scale[0] = 0.125f; ga.scale[1] = 1.0f; ga.scale[2] = 1.0f;
    ga.mode[0] = 1; ga.mode[1] = 1; ga.mode[2] = 2;
    gemm_hmma<<<dim3(8, 32, 3), 256, GDYN>>>(ga);

    wg_kernel<<<dim3(NN, NB), 256>>>(box, Wg, bg);

    attn_flash<<<NB * NH * 2, 256, AF_TOT>>>();

    GArgs go;
    go.Ah = pah; go.Al = pal;
    go.Bh = pwh + 3 * DDIM * DDIM; go.Bl = pwl + 3 * DDIM * DDIM;
    go.bias[0] = go.bias[1] = go.bias[2] = bo;
    go.C[0] = go.C[1] = go.C[2] = out;
    go.Oh[0] = go.Oh[1] = go.Oh[2] = nullptr;
    go.Ol[0] = go.Ol[1] = go.Ol[2] = nullptr;
    go.scale[0] = go.scale[1] = go.scale[2] = 1.0f;
    go.mode[0] = go.mode[1] = go.mode[2] = 0;
    gemm_hmma<<<dim3(8, 32, 1), 256, GDYN>>>(go);
}

// round 14
// speedup vs baseline: 1.1397x; 1.0178x over previous
#include <cuda_runtime.h>
#include <cuda_bf16.h>
#include <math.h>
#include <stdint.h>

#define NB 16
#define NN 256
#define DDIM 512
#define NH 8
#define DKH 64
#define MROWS (NB*NN)        // 4096

// ---------------- scratch ----------------
__device__ float g_wgl[NB*NH*NN*NN];
__device__ __nv_bfloat16 g_wTh[4*DDIM*DDIM];
__device__ __nv_bfloat16 g_wTl[4*DDIM*DDIM];
__device__ __nv_bfloat16 g_ah[3*MROWS*DDIM];
__device__ __nv_bfloat16 g_al[3*MROWS*DDIM];
__device__ __nv_bfloat16 g_qh[NB*NH*NN*DKH], g_ql[NB*NH*NN*DKH];
__device__ __nv_bfloat16 g_kh[NB*NH*NN*DKH], g_kl[NB*NH*NN*DKH];
__device__ __nv_bfloat16 g_vh[NB*NH*DKH*NN], g_vl[NB*NH*DKH*NN];

// =========================== helpers ================================
__device__ __forceinline__ uint32_t smem_u32(const void* p) {
    uint32_t a;
    asm("{ .reg .u64 t; cvta.to.shared.u64 t, %1; cvt.u32.u64 %0, t; }" : "=r"(a) : "l"(p));
    return a;
}
__device__ __forceinline__ void ldsm4(uint32_t* r, uint32_t addr) {
    asm volatile("ldmatrix.sync.aligned.m8n8.x4.shared.b16 {%0,%1,%2,%3}, [%4];"
                 : "=r"(r[0]), "=r"(r[1]), "=r"(r[2]), "=r"(r[3]) : "r"(addr));
}
__device__ __forceinline__ void mma16816(float* d, const uint32_t* a, uint32_t b0, uint32_t b1) {
    asm volatile("mma.sync.aligned.m16n8k16.row.col.f32.bf16.bf16.f32 "
                 "{%0,%1,%2,%3}, {%4,%5,%6,%7}, {%8,%9}, {%0,%1,%2,%3};"
                 : "+f"(d[0]), "+f"(d[1]), "+f"(d[2]), "+f"(d[3])
                 : "r"(a[0]), "r"(a[1]), "r"(a[2]), "r"(a[3]), "r"(b0), "r"(b1));
}
#define CPA16(dst, src) \
    asm volatile("cp.async.cg.shared.global [%0], [%1], 16;" :: "r"(dst), "l"(src) : "memory")
#define CPCOMMIT() asm volatile("cp.async.commit_group;" ::: "memory")
#define CPWAIT1()  asm volatile("cp.async.wait_group 1;" ::: "memory")
#define CPWAIT0()  asm volatile("cp.async.wait_group 0;" ::: "memory")

__device__ __forceinline__ void bsplit2(float x, float y, uint32_t& h, uint32_t& l) {
    __nv_bfloat162 hh = __floats2bfloat162_rn(x, y);
    float2 r = __bfloat1622float2(hh);
    __nv_bfloat162 ll = __floats2bfloat162_rn(x - r.x, y - r.y);
    h = *(uint32_t*)&hh; l = *(uint32_t*)&ll;
}
__device__ __forceinline__ void bsplit1(float x, __nv_bfloat16& h, __nv_bfloat16& l) {
    h = __float2bfloat16_rn(x);
    l = __float2bfloat16_rn(x - __bfloat162float(h));
}
__device__ __forceinline__ void ffma2(uint64_t& acc, uint64_t a, uint64_t b) {
    asm("fma.rn.f32x2 %0, %1, %2, %0;" : "+l"(acc) : "l"(a), "l"(b));
}
__device__ __forceinline__ uint64_t pack2(float x) {
    uint64_t r; asm("mov.b64 %0, {%1, %1};" : "=l"(r) : "f"(x)); return r;
}
__device__ __forceinline__ float2 unpack2(uint64_t v) {
    float2 f; asm("mov.b64 {%0, %1}, %2;" : "=f"(f.x), "=f"(f.y) : "l"(v)); return f;
}

// =================================================================================
// Fused prep: weight transpose/split (blocks 0..1023) + input split (1024..7167)
// =================================================================================
__global__ __launch_bounds__(256)
void prep_kernel(const float* __restrict__ w0, const float* __restrict__ w1,
                 const float* __restrict__ w2, const float* __restrict__ w3,
                 const float* __restrict__ q, const float* __restrict__ k,
                 const float* __restrict__ v)
{
    __shared__ float tile[32][33];
    const int bx = blockIdx.x, t = threadIdx.x;
    if (bx < 1024) {
        const int z = bx >> 8, xy = bx & 255;
        const float* W = (z == 0) ? w0 : (z == 1) ? w1 : (z == 2) ? w2 : w3;
        __nv_bfloat16* Th = g_wTh + z * (DDIM * DDIM);
        __nv_bfloat16* Tl = g_wTl + z * (DDIM * DDIM);
        const int x0 = (xy & 15) * 32, y0 = (xy >> 4) * 32;
        const int tx = t & 31, ty = t >> 5;
        #pragma unroll
        for (int r = ty; r < 32; r += 8)
            tile[r][tx] = W[(y0 + r) * DDIM + x0 + tx];
        __syncthreads();
        #pragma unroll
        for (int r = ty; r < 32; r += 8) {
            float vv = tile[tx][r];
            __nv_bfloat16 h, l; bsplit1(vv, h, l);
            Th[(x0 + r) * DDIM + y0 + tx] = h;
            Tl[(x0 + r) * DDIM + y0 + tx] = l;
        }
    } else {
        const int idx = bx - 1024;            // 0..6143
        const int z = idx / 2048, blk = idx % 2048;
        const float* src = (z == 0) ? q : (z == 1) ? k : v;
        __nv_bfloat16* oh = g_ah + z * (MROWS * DDIM);
        __nv_bfloat16* ol = g_al + z * (MROWS * DDIM);
        const int i4 = blk * 256 + t;
        float4 f = ((const float4*)src)[i4];
        uint32_t h0, l0, h1, l1;
        bsplit2(f.x, f.y, h0, l0);
        bsplit2(f.z, f.w, h1, l1);
        ((uint2*)oh)[i4] = make_uint2(h0, h1);
        ((uint2*)ol)[i4] = make_uint2(l0, l1);
    }
}

// =================================================================================
// HMMA GEMM (bf16 split, 3 passes). BM=128, BN=64, BK=32, 3-stage, 2 CTAs/SM.
// =================================================================================
#define BK 32
#define STG 3
#define ROWB 80
#define MAT_A (128*ROWB)
#define MAT_Bb (64*ROWB)
#define STG_B (2*MAT_A + 2*MAT_Bb)
#define GDYN (STG*STG_B)

struct GArgs {
    const __nv_bfloat16 *Ah, *Al, *Bh, *Bl;
    const float* bias[3];
    float*       C[3];
    __nv_bfloat16 *Oh[3], *Ol[3];
    float scale[3];
    int mode[3];
};

__global__ __launch_bounds__(256, 2)
void gemm_hmma(const GArgs args)
{
    extern __shared__ char smraw[];
    const uint32_t sb = smem_u32(smraw);
    const int t = threadIdx.x, lane = t & 31, wid = t >> 5;
    const int wm = wid & 3, wn = wid >> 2;
    const int z = blockIdx.z;
    const int r0 = blockIdx.y * 128, c0 = blockIdx.x * 64;

    const __nv_bfloat16* pAh = args.Ah + (size_t)z * MROWS * DDIM;
    const __nv_bfloat16* pAl = args.Al + (size_t)z * MROWS * DDIM;
    const __nv_bfloat16* pBh = args.Bh + (size_t)z * DDIM * DDIM;
    const __nv_bfloat16* pBl = args.Bl + (size_t)z * DDIM * DDIM;
    const float* bias = args.bias[z];

    const int row_a = t >> 2, ch = t & 3;
    auto load_stage = [&](int kt) {
        uint32_t dstS = sb + (uint32_t)(kt % STG) * STG_B;
        int k0 = kt * BK + ch * 8;
        #pragma unroll
        for (int it = 0; it < 2; it++) {
            int row = row_a + it * 64;
            uint32_t d = dstS + row * ROWB + ch * 16;
            CPA16(d,          pAh + (r0 + row) * DDIM + k0);
            CPA16(d + MAT_A,  pAl + (r0 + row) * DDIM + k0);
        }
        uint32_t d2 = dstS + 2 * MAT_A + row_a * ROWB + ch * 16;
        CPA16(d2,           pBh + (c0 + row_a) * DDIM + k0);
        CPA16(d2 + MAT_Bb,  pBl + (c0 + row_a) * DDIM + k0);
        CPCOMMIT();
    };

    float acc[2][4][4];
    #pragma unroll
    for (int mt = 0; mt < 2; mt++)
        #pragma unroll
        for (int nt = 0; nt < 4; nt++)
            #pragma unroll
            for (int i = 0; i < 4; i++) acc[mt][nt][i] = 0.0f;

    load_stage(0);
    load_stage(1);

    const uint32_t aRowOff = (uint32_t)(wm * 32 + (lane & 15)) * ROWB;
    const uint32_t aColOff = (uint32_t)(((lane >> 4) & 1) << 4);
    const uint32_t bRowOff = (uint32_t)(wn * 32 + (((lane >> 4) & 1) << 3) + (lane & 7)) * ROWB;
    const uint32_t bColOff = (uint32_t)(((lane >> 3) & 1) << 4);

    for (int kt = 0; kt < DDIM / BK; kt++) {
        CPWAIT1();
        __syncthreads();
        if (kt + 2 < DDIM / BK) load_stage(kt + 2);
        const uint32_t SB = sb + (uint32_t)(kt % STG) * STG_B;
        #pragma unroll
        for (int kk = 0; kk < 2; kk++) {
            const uint32_t k16b = (uint32_t)(kk * 32);
            uint32_t ah[2][4], al[2][4], fbh[2][4], fbl[2][4];
            uint32_t aA = SB + aRowOff + k16b + aColOff;
            ldsm4(ah[0], aA);
            ldsm4(ah[1], aA + 16 * ROWB);
            ldsm4(al[0], aA + MAT_A);
            ldsm4(al[1], aA + MAT_A + 16 * ROWB);
            uint32_t bA = SB + 2 * MAT_A + bRowOff + k16b + bColOff;
            #pragma unroll
            for (int n16 = 0; n16 < 2; n16++) {
                ldsm4(fbh[n16], bA + n16 * 16 * ROWB);
                ldsm4(fbl[n16], bA + MAT_Bb + n16 * 16 * ROWB);
            }
            #pragma unroll
            for (int mt = 0; mt < 2; mt++)
                #pragma unroll
                for (int nt = 0; nt < 4; nt++) {
                    const uint32_t* bph = &fbh[nt >> 1][(nt & 1) * 2];
                    const uint32_t* bpl = &fbl[nt >> 1][(nt & 1) * 2];
                    mma16816(acc[mt][nt], ah[mt], bph[0], bph[1]);
                    mma16816(acc[mt][nt], ah[mt], bpl[0], bpl[1]);
                    mma16816(acc[mt][nt], al[mt], bph[0], bph[1]);
                }
        }
    }

    const int md = args.mode[z];
    const float sc = args.scale[z];
    #pragma unroll
    for (int mt = 0; mt < 2; mt++) {
        int row0 = r0 + wm * 32 + mt * 16 + (lane >> 2);
        #pragma unroll
        for (int nt = 0; nt < 4; nt++) {
            int col = c0 + wn * 32 + nt * 8 + (lane & 3) * 2;
            float2 bs = *(const float2*)&bias[col];
            float v0 = (acc[mt][nt][0] + bs.x) * sc;
            float v1 = (acc[mt][nt][1] + bs.y) * sc;
            float v2 = (acc[mt][nt][2] + bs.x) * sc;
            float v3 = (acc[mt][nt][3] + bs.y) * sc;
            if (md == 0) {
                float* C = args.C[z];
                *(float2*)&C[row0 * DDIM + col] = make_float2(v0, v1);
                *(float2*)&C[(row0 + 8) * DDIM + col] = make_float2(v2, v3);
            } else if (md == 1) {
                __nv_bfloat16* Oh = args.Oh[z]; __nv_bfloat16* Ol = args.Ol[z];
                int hh = col >> 6, d = col & 63;
                uint32_t u0h, u0l, u1h, u1l;
                bsplit2(v0, v1, u0h, u0l);
                bsplit2(v2, v3, u1h, u1l);
                int b0i = row0 >> 8, n0i = row0 & 255;
                size_t i0x = (size_t)(((b0i * NH + hh) * NN + n0i) * DKH + d);
                *(uint32_t*)(Oh + i0x) = u0h; *(uint32_t*)(Ol + i0x) = u0l;
                int r1i = row0 + 8;
                int b1i = r1i >> 8, n1i = r1i & 255;
                size_t i1x = (size_t)(((b1i * NH + hh) * NN + n1i) * DKH + d);
                *(uint32_t*)(Oh + i1x) = u1h; *(uint32_t*)(Ol + i1x) = u1l;
            } else {
                __nv_bfloat16* Oh = args.Oh[z]; __nv_bfloat16* Ol = args.Ol[z];
                int hh = col >> 6, d = col & 63;
                int b0i = row0 >> 8, n0i = row0 & 255;
                size_t base = (size_t)(((b0i * NH + hh) * DKH + d) * NN + n0i);
                __nv_bfloat16 h, l;
                bsplit1(v0, h, l); Oh[base] = h;           Ol[base] = l;
                bsplit1(v1, h, l); Oh[base + NN] = h;      Ol[base + NN] = l;
                bsplit1(v2, h, l); Oh[base + 8] = h;       Ol[base + 8] = l;
                bsplit1(v3, h, l); Oh[base + NN + 8] = h;  Ol[base + NN + 8] = l;
            }
        }
    }
}

// =================================================================================
// Geometry gate v4: block = 2 i-rows x 128 threads; each thread does 2 adjacent j.
// Weight LDS shared across both j; float2 stores.
// =================================================================================
__global__ __launch_bounds__(256)
void wg_kernel(const float* __restrict__ box, const float* __restrict__ Wg,
               const float* __restrict__ bg)
{
    __shared__ __align__(16) float WgT[64][8];
    __shared__ __align__(16) float bgs[8];
    __shared__ float istat[2][6];

    const int b = blockIdx.y, t = threadIdx.x;
    const int iw = t >> 7, tj = t & 127;
    const int i = blockIdx.x * 2 + iw;

    for (int idx = t; idx < 512; idx += 256) {
        int g = idx >> 3, h = idx & 7;
        WgT[g][h] = Wg[h * 64 + g];
    }
    if (t < 8) bgs[t] = bg[t];
    if (t < 2) {
        float4 bx = *(const float4*)&box[(b*NN + blockIdx.x * 2 + t) * 4];
        float cx = 0.5f * (bx.x + bx.z), cy = 0.5f * (bx.y + bx.w);
        float w = bx.z - bx.x + 1.0f,   h = bx.w - bx.y + 1.0f;
        istat[t][0] = cx; istat[t][1] = cy; istat[t][2] = w; istat[t][3] = h;
        istat[t][4] = __logf(w); istat[t][5] = __logf(h);
    }
    __syncthreads();

    const int j0 = tj * 2;
    float4 bj0 = *(const float4*)&box[(b*NN + j0) * 4];
    float4 bj1 = *(const float4*)&box[(b*NN + j0 + 1) * 4];

    const float icx = istat[iw][0], icy = istat[iw][1];
    const float iw2 = istat[iw][2], ih2 = istat[iw][3];
    const float ilw = istat[iw][4], ilh = istat[iw][5];

    float angA[4], angB[4];
    {
        float cxj = 0.5f * (bj0.x + bj0.z), cyj = 0.5f * (bj0.y + bj0.w);
        float wj = bj0.z - bj0.x + 1.0f,    hj = bj0.w - bj0.y + 1.0f;
        angA[0] = 100.0f * __logf(fmaxf(fabsf(icx - cxj) / iw2, 1e-3f));
        angA[1] = 100.0f * __logf(fmaxf(fabsf(icy - cyj) / ih2, 1e-3f));
        angA[2] = 100.0f * (ilw - __logf(wj));
        angA[3] = 100.0f * (ilh - __logf(hj));
    }
    {
        float cxj = 0.5f * (bj1.x + bj1.z), cyj = 0.5f * (bj1.y + bj1.w);
        float wj = bj1.z - bj1.x + 1.0f,    hj = bj1.w - bj1.y + 1.0f;
        angB[0] = 100.0f * __logf(fmaxf(fabsf(icx - cxj) / iw2, 1e-3f));
        angB[1] = 100.0f * __logf(fmaxf(fabsf(icy - cyj) / ih2, 1e-3f));
        angB[2] = 100.0f * (ilw - __logf(wj));
        angB[3] = 100.0f * (ilh - __logf(hj));
    }

    const float dimf[8] = {1.0f, 0.42169650342f, 0.17782794100f, 0.07498942093f,
                           0.03162277660f, 0.01333521432f, 0.00562341325f, 0.00237137371f};

    uint64_t A01 = *(const uint64_t*)&bgs[0], A23 = *(const uint64_t*)&bgs[2];
    uint64_t A45 = *(const uint64_t*)&bgs[4], A67 = *(const uint64_t*)&bgs[6];
    uint64_t B01 = A01, B23 = A23, B45 = A45, B67 = A67;

    #pragma unroll
    for (int g = 0; g < 32; g++) {
        const float df = dimf[g & 7];
        ulonglong2 wsA = *(const ulonglong2*)&WgT[g][0];
        ulonglong2 wsB = *(const ulonglong2*)&WgT[g][4];
        ulonglong2 wcA = *(const ulonglong2*)&WgT[32 + g][0];
        ulonglong2 wcB = *(const ulonglong2*)&WgT[32 + g][4];
        // pair A
        {
            float th = angA[g >> 3] * df;
            float n = rintf(th * 0.15915494309189535f);
            float r = fmaf(n, -6.283185482025146f, th);
            r = fmaf(n, 1.7484555e-7f, r);
            float s, co;
            __sincosf(r, &s, &co);
            uint64_t s2 = pack2(s), c2 = pack2(co);
            ffma2(A01, s2, wsA.x); ffma2(A23, s2, wsA.y);
            ffma2(A45, s2, wsB.x); ffma2(A67, s2, wsB.y);
            ffma2(A01, c2, wcA.x); ffma2(A23, c2, wcA.y);
            ffma2(A45, c2, wcB.x); ffma2(A67, c2, wcB.y);
        }
        // pair B
        {
            float th = angB[g >> 3] * df;
            float n = rintf(th * 0.15915494309189535f);
            float r = fmaf(n, -6.283185482025146f, th);
            r = fmaf(n, 1.7484555e-7f, r);
            float s, co;
            __sincosf(r, &s, &co);
            uint64_t s2 = pack2(s), c2 = pack2(co);
            ffma2(B01, s2, wsA.x); ffma2(B23, s2, wsA.y);
            ffma2(B45, s2, wsB.x); ffma2(B67, s2, wsB.y);
            ffma2(B01, c2, wcA.x); ffma2(B23, c2, wcA.y);
            ffma2(B45, c2, wcB.x); ffma2(B67, c2, wcB.y);
        }
    }

    float2 a01 = unpack2(A01), a23 = unpack2(A23), a45 = unpack2(A45), a67 = unpack2(A67);
    float2 b01 = unpack2(B01), b23 = unpack2(B23), b45 = unpack2(B45), b67 = unpack2(B67);
    float av[8] = {a01.x, a01.y, a23.x, a23.y, a45.x, a45.y, a67.x, a67.y};
    float bv[8] = {b01.x, b01.y, b23.x, b23.y, b45.x, b45.y, b67.x, b67.y};
    const int base = ((b*NH) * NN + i) * NN + j0;
    #pragma unroll
    for (int h = 0; h < 8; h++) {
        float2 o;
        o.x = __logf(fmaxf(av[h], 1e-6f));
        o.y = __logf(fmaxf(bv[h], 1e-6f));
        *(float2*)&g_wgl[base + h * (NN*NN)] = o;
    }
}

// =================================================================================
// Flash attention (unchanged from R12)
// =================================================================================
#define AF_QH 0
#define AF_QL 16384
#define AF_KV 32768
#define AF_STAGE 32768
#define AF_TOT (AF_KV + 2*AF_STAGE)   // 98304

__global__ __launch_bounds__(256, 2)
void attn_flash()
{
    extern __shared__ char sm[];
    const uint32_t sb = smem_u32(sm);
    const int t = threadIdx.x, lane = t & 31, w = t >> 5;
    const int bh = blockIdx.x >> 1, half = blockIdx.x & 1;
    const __nv_bfloat16* kh = g_kh + (size_t)bh * NN * DKH;
    const __nv_bfloat16* kl = g_kl + (size_t)bh * NN * DKH;
    const __nv_bfloat16* vh = g_vh + (size_t)bh * DKH * NN;
    const __nv_bfloat16* vl = g_vl + (size_t)bh * DKH * NN;
    const __nv_bfloat16* qh = g_qh + (size_t)bh * NN * DKH + (size_t)half * 128 * DKH;
    const __nv_bfloat16* ql = g_ql + (size_t)bh * NN * DKH + (size_t)half * 128 * DKH;
    const float* wglb = g_wgl + (size_t)bh * NN * NN + (size_t)(half * 128) * NN;

    #pragma unroll
    for (int p = 0; p < 4; p++) {
        int idx = t + p * 256; int r = idx >> 3, c = idx & 7;
        uint32_t off = ((uint32_t)(r * 128 + c * 16)) ^ ((uint32_t)(r & 7) << 4);
        CPA16(sb + AF_QH + off, qh + r * 64 + c * 8);
        CPA16(sb + AF_QL + off, ql + r * 64 + c * 8);
    }
    auto load_kv = [&](int kt) {
        int j0 = kt * 64;
        uint32_t dst = sb + AF_KV + (uint32_t)(kt & 1) * AF_STAGE;
        #pragma unroll
        for (int p = 0; p < 2; p++) {
            int idx = t + p * 256; int r = idx >> 3, c = idx & 7;
            uint32_t off = ((uint32_t)(r * 128 + c * 16)) ^ ((uint32_t)(r & 7) << 4);
            CPA16(dst + off,          kh + (j0 + r) * 64 + c * 8);
            CPA16(dst + 8192 + off,   kl + (j0 + r) * 64 + c * 8);
            CPA16(dst + 16384 + off,  vh + r * 256 + j0 + c * 8);
            CPA16(dst + 24576 + off,  vl + r * 256 + j0 + c * 8);
        }
        CPCOMMIT();
    };
    load_kv(0);
    load_kv(1);

    const uint32_t swz = (uint32_t)(lane & 7) << 4;
    const uint32_t aoffBase = (uint32_t)((w * 16 + (lane & 15)) * 128 + ((lane >> 4) & 1) * 16);
    const uint32_t boffBase = (uint32_t)(((((lane >> 4) & 1) * 8) + (lane & 7)) * 128 + ((lane >> 3) & 1) * 16);

    float mprev0 = -1e30f, mprev1 = -1e30f;
    float ssum0 = 0.0f, ssum1 = 0.0f;
    float oacc[8][4];
    #pragma unroll
    for (int nt = 0; nt < 8; nt++)
        #pragma unroll
        for (int u = 0; u < 4; u++) oacc[nt][u] = 0.0f;

    #pragma unroll
    for (int kt = 0; kt < 4; kt++) {
        if (kt == 3) { CPWAIT0(); } else { CPWAIT1(); }
        __syncthreads();
        const uint32_t KB = sb + AF_KV + (uint32_t)(kt & 1) * AF_STAGE;

        float acc[8][4];
        #pragma unroll
        for (int nt = 0; nt < 8; nt++)
            #pragma unroll
            for (int u = 0; u < 4; u++) acc[nt][u] = 0.0f;

        #pragma unroll
        for (int ks = 0; ks < 4; ks++) {
            uint32_t ah[4], al[4];
            uint32_t aA = (aoffBase + (uint32_t)(ks * 32)) ^ swz;
            ldsm4(ah, sb + AF_QH + aA);
            ldsm4(al, sb + AF_QL + aA);
            uint32_t bA = (boffBase + (uint32_t)(ks * 32)) ^ swz;
            #pragma unroll
            for (int n16 = 0; n16 < 4; n16++) {
                uint32_t fbh[4], fbl[4];
                ldsm4(fbh, KB + bA + n16 * 2048);
                ldsm4(fbl, KB + 8192 + bA + n16 * 2048);
                #pragma unroll
                for (int q = 0; q < 2; q++) {
                    int nt = n16 * 2 + q;
                    mma16816(acc[nt], ah, fbh[q*2], fbh[q*2+1]);
                    mma16816(acc[nt], ah, fbl[q*2], fbl[q*2+1]);
                    mma16816(acc[nt], al, fbh[q*2], fbh[q*2+1]);
                }
            }
        }

        {
            int rA = w * 16 + (lane >> 2);
            const float* w0p = wglb + (size_t)rA * NN + kt * 64 + (lane & 3) * 2;
            const float* w1p = w0p + 8 * NN;
            #pragma unroll
            for (int nt = 0; nt < 8; nt++) {
                float2 g0 = *(const float2*)(w0p + nt * 8);
                float2 g1 = *(const float2*)(w1p + nt * 8);
                acc[nt][0] += g0.x; acc[nt][1] += g0.y;
                acc[nt][2] += g1.x; acc[nt][3] += g1.y;
            }
        }

        float mt0 = -1e30f, mt1 = -1e30f;
        #pragma unroll
        for (int nt = 0; nt < 8; nt++) {
            mt0 = fmaxf(mt0, fmaxf(acc[nt][0], acc[nt][1]));
            mt1 = fmaxf(mt1, fmaxf(acc[nt][2], acc[nt][3]));
        }
        #pragma unroll
        for (int off = 1; off <= 2; off <<= 1) {
            mt0 = fmaxf(mt0, __shfl_xor_sync(~0u, mt0, off));
            mt1 = fmaxf(mt1, __shfl_xor_sync(~0u, mt1, off));
        }
        float mn0 = fmaxf(mprev0, mt0), mn1 = fmaxf(mprev1, mt1);
        float f0 = __expf(mprev0 - mn0), f1 = __expf(mprev1 - mn1);
        mprev0 = mn0; mprev1 = mn1;
        float ls0 = 0.0f, ls1 = 0.0f;
        #pragma unroll
        for (int nt = 0; nt < 8; nt++) {
            acc[nt][0] = __expf(acc[nt][0] - mn0);
            acc[nt][1] = __expf(acc[nt][1] - mn0);
            acc[nt][2] = __expf(acc[nt][2] - mn1);
            acc[nt][3] = __expf(acc[nt][3] - mn1);
            ls0 += acc[nt][0] + acc[nt][1];
            ls1 += acc[nt][2] + acc[nt][3];
            oacc[nt][0] *= f0; oacc[nt][1] *= f0;
            oacc[nt][2] *= f1; oacc[nt][3] *= f1;
        }
        #pragma unroll
        for (int off = 1; off <= 2; off <<= 1) {
            ls0 += __shfl_xor_sync(~0u, ls0, off);
            ls1 += __shfl_xor_sync(~0u, ls1, off);
        }
        ssum0 = ssum0 * f0 + ls0;
        ssum1 = ssum1 * f1 + ls1;

        #pragma unroll
        for (int kt2 = 0; kt2 < 4; kt2++) {
            uint32_t aph[4], apl[4];
            bsplit2(acc[2*kt2][0],   acc[2*kt2][1],   aph[0], apl[0]);
            bsplit2(acc[2*kt2][2],   acc[2*kt2][3],   aph[1], apl[1]);
            bsplit2(acc[2*kt2+1][0], acc[2*kt2+1][1], aph[2], apl[2]);
            bsplit2(acc[2*kt2+1][2], acc[2*kt2+1][3], aph[3], apl[3]);
            uint32_t bA = (boffBase + (uint32_t)(kt2 * 32)) ^ swz;
            #pragma unroll
            for (int n16 = 0; n16 < 4; n16++) {
                uint32_t vbh[4], vbl[4];
                ldsm4(vbh, KB + 16384 + bA + n16 * 2048);
                ldsm4(vbl, KB + 24576 + bA + n16 * 2048);
                #pragma unroll
                for (int q = 0; q < 2; q++) {
                    int nt = n16 * 2 + q;
                    mma16816(oacc[nt], aph, vbh[q*2], vbh[q*2+1]);
                    mma16816(oacc[nt], aph, vbl[q*2], vbl[q*2+1]);
                    mma16816(oacc[nt], apl, vbh[q*2], vbh[q*2+1]);
                }
            }
        }
        __syncthreads();
        if (kt < 2) load_kv(kt + 2);
    }

    {
        float inv0 = 1.0f / ssum0, inv1 = 1.0f / ssum1;
        int rA = w * 16 + (lane >> 2);
        int orow = (bh >> 3) * NN + half * 128 + rA;
        int ocol = (bh & 7) * DKH + (lane & 3) * 2;
        #pragma unroll
        for (int nt = 0; nt < 8; nt++) {
            float v0 = oacc[nt][0] * inv0, v1 = oacc[nt][1] * inv0;
            float v2 = oacc[nt][2] * inv1, v3 = oacc[nt][3] * inv1;
            uint32_t h0, l0, h1, l1;
            bsplit2(v0, v1, h0, l0);
            bsplit2(v2, v3, h1, l1);
            size_t i0x = (size_t)orow * DDIM + ocol + nt * 8;
            size_t i1x = (size_t)(orow + 8) * DDIM + ocol + nt * 8;
            *(uint32_t*)(g_ah + i0x) = h0; *(uint32_t*)(g_al + i0x) = l0;
            *(uint32_t*)(g_ah + i1x) = h1; *(uint32_t*)(g_al + i1x) = l1;
        }
    }
}

// =================================================================================
// launch
// =================================================================================
extern "C" void kernel_launch(void* const* d_in, const int* in_sizes, int n_in,
                              void* d_out, int out_size)
{
    const float* query = (const float*)d_in[0];
    const float* key   = (const float*)d_in[1];
    const float* value = (const float*)d_in[2];
    const float* box   = (const float*)d_in[3];
    const float* Wq = (const float*)d_in[4];
    const float* bq = (const float*)d_in[5];
    const float* Wk = (const float*)d_in[6];
    const float* bk = (const float*)d_in[7];
    const float* Wv = (const float*)d_in[8];
    const float* bv = (const float*)d_in[9];
    const float* Wo = (const float*)d_in[10];
    const float* bo = (const float*)d_in[11];
    const float* Wg = (const float*)d_in[12];
    const float* bg = (const float*)d_in[13];
    float* out = (float*)d_out;

    __nv_bfloat16 *pah, *pal, *pwh, *pwl, *pqh, *pql, *pkh, *pkl, *pvh, *pvl;
    cudaGetSymbolAddress((void**)&pah, g_ah);
    cudaGetSymbolAddress((void**)&pal, g_al);
    cudaGetSymbolAddress((void**)&pwh, g_wTh);
    cudaGetSymbolAddress((void**)&pwl, g_wTl);
    cudaGetSymbolAddress((void**)&pqh, g_qh);
    cudaGetSymbolAddress((void**)&pql, g_ql);
    cudaGetSymbolAddress((void**)&pkh, g_kh);
    cudaGetSymbolAddress((void**)&pkl, g_kl);
    cudaGetSymbolAddress((void**)&pvh, g_vh);
    cudaGetSymbolAddress((void**)&pvl, g_vl);

    static bool attr_set = false;
    if (!attr_set) {
        cudaFuncSetAttribute(gemm_hmma, cudaFuncAttributeMaxDynamicSharedMemorySize, GDYN);
        cudaFuncSetAttribute(attn_flash, cudaFuncAttributeMaxDynamicSharedMemorySize, AF_TOT);
        attr_set = true;
    }

    // fused prep: weight transpose/split + input split
    prep_kernel<<<7168, 256>>>(Wq, Wk, Wv, Wo, query, key, value);

    GArgs ga;
    ga.Ah = pah; ga.Al = pal; ga.Bh = pwh; ga.Bl = pwl;
    ga.bias[0] = bq; ga.bias[1] = bk; ga.bias[2] = bv;
    ga.C[0] = ga.C[1] = ga.C[2] = nullptr;
    ga.Oh[0] = pqh; ga.Ol[0] = pql;
    ga.Oh[1] = pkh; ga.Ol[1] = pkl;
    ga.Oh[2] = pvh; ga.Ol[2] = pvl;
    ga.scale[0] = 0.125f; ga.scale[1] = 1.0f; ga.scale[2] = 1.0f;
    ga.mode[0] = 1; ga.mode[1] = 1; ga.mode[2] = 2;
    gemm_hmma<<<dim3(8, 32, 3), 256, GDYN>>>(ga);

    wg_kernel<<<dim3(NN/2, NB), 256>>>(box, Wg, bg);

    attn_flash<<<NB * NH * 2, 256, AF_TOT>>>();

    GArgs go;
    go.Ah = pah; go.Al = pal;
    go.Bh = pwh + 3 * DDIM * DDIM; go.Bl = pwl + 3 * DDIM * DDIM;
    go.bias[0] = go.bias[1] = go.bias[2] = bo;
    go.C[0] = go.C[1] = go.C[2] = out;
    go.Oh[0] = go.Oh[1] = go.Oh[2] = nullptr;
    go.Ol[0] = go.Ol[1] = go.Ol[2] = nullptr;
    go.scale[0] = go.scale[1] = go.scale[2] = 1.0f;
    go.mode[0] = go.mode[1] = go.mode[2] = 0;
    gemm_hmma<<<dim3(8, 32, 1), 256, GDYN>>>(go);
}

// round 16
// speedup vs baseline: 1.1638x; 1.0212x over previous
#include <cuda_runtime.h>
#include <cuda_bf16.h>
#include <math.h>
#include <stdint.h>

#define NB 16
#define NN 256
#define DDIM 512
#define NH 8
#define DKH 64
#define MROWS (NB*NN)        // 4096

// ---------------- scratch ----------------
__device__ float g_wgl[NB*NH*NN*NN];
__device__ __nv_bfloat16 g_wTh[4*DDIM*DDIM];
__device__ __nv_bfloat16 g_wTl[4*DDIM*DDIM];
__device__ __nv_bfloat16 g_ah[3*MROWS*DDIM];
__device__ __nv_bfloat16 g_al[3*MROWS*DDIM];
__device__ __nv_bfloat16 g_qh[NB*NH*NN*DKH], g_ql[NB*NH*NN*DKH];
__device__ __nv_bfloat16 g_kh[NB*NH*NN*DKH], g_kl[NB*NH*NN*DKH];
__device__ __nv_bfloat16 g_vh[NB*NH*DKH*NN], g_vl[NB*NH*DKH*NN];

// =========================== helpers ================================
__device__ __forceinline__ uint32_t smem_u32(const void* p) {
    uint32_t a;
    asm("{ .reg .u64 t; cvta.to.shared.u64 t, %1; cvt.u32.u64 %0, t; }" : "=r"(a) : "l"(p));
    return a;
}
__device__ __forceinline__ void ldsm4(uint32_t* r, uint32_t addr) {
    asm volatile("ldmatrix.sync.aligned.m8n8.x4.shared.b16 {%0,%1,%2,%3}, [%4];"
                 : "=r"(r[0]), "=r"(r[1]), "=r"(r[2]), "=r"(r[3]) : "r"(addr));
}
__device__ __forceinline__ void mma16816(float* d, const uint32_t* a, uint32_t b0, uint32_t b1) {
    asm volatile("mma.sync.aligned.m16n8k16.row.col.f32.bf16.bf16.f32 "
                 "{%0,%1,%2,%3}, {%4,%5,%6,%7}, {%8,%9}, {%0,%1,%2,%3};"
                 : "+f"(d[0]), "+f"(d[1]), "+f"(d[2]), "+f"(d[3])
                 : "r"(a[0]), "r"(a[1]), "r"(a[2]), "r"(a[3]), "r"(b0), "r"(b1));
}
#define CPA16(dst, src) \
    asm volatile("cp.async.cg.shared.global [%0], [%1], 16;" :: "r"(dst), "l"(src) : "memory")
#define CPCOMMIT() asm volatile("cp.async.commit_group;" ::: "memory")
#define CPWAIT1()  asm volatile("cp.async.wait_group 1;" ::: "memory")
#define CPWAIT0()  asm volatile("cp.async.wait_group 0;" ::: "memory")

__device__ __forceinline__ void bsplit2(float x, float y, uint32_t& h, uint32_t& l) {
    __nv_bfloat162 hh = __floats2bfloat162_rn(x, y);
    float2 r = __bfloat1622float2(hh);
    __nv_bfloat162 ll = __floats2bfloat162_rn(x - r.x, y - r.y);
    h = *(uint32_t*)&hh; l = *(uint32_t*)&ll;
}
__device__ __forceinline__ void bsplit1(float x, __nv_bfloat16& h, __nv_bfloat16& l) {
    h = __float2bfloat16_rn(x);
    l = __float2bfloat16_rn(x - __bfloat162float(h));
}
__device__ __forceinline__ void ffma2(uint64_t& acc, uint64_t a, uint64_t b) {
    asm("fma.rn.f32x2 %0, %1, %2, %0;" : "+l"(acc) : "l"(a), "l"(b));
}
__device__ __forceinline__ uint64_t pack2(float x) {
    uint64_t r; asm("mov.b64 %0, {%1, %1};" : "=l"(r) : "f"(x)); return r;
}
__device__ __forceinline__ float2 unpack2(uint64_t v) {
    float2 f; asm("mov.b64 {%0, %1}, %2;" : "=f"(f.x), "=f"(f.y) : "l"(v)); return f;
}

// =================================================================================
// Fused stage-1 kernel: wg blocks [0, 2048) first, then weight-transpose blocks
// [2048, 3072), then input-split blocks [3072, 9216).
// wg: block = 2 i-rows x 128 j-threads (2 j per thread), same numerics as R14.
// =================================================================================
__global__ __launch_bounds__(256)
void stage1_kernel(const float* __restrict__ box, const float* __restrict__ Wg,
                   const float* __restrict__ bg,
                   const float* __restrict__ w0, const float* __restrict__ w1,
                   const float* __restrict__ w2, const float* __restrict__ w3,
                   const float* __restrict__ q, const float* __restrict__ k,
                   const float* __restrict__ v)
{
    const int bx = blockIdx.x, t = threadIdx.x;

    if (bx < 2048) {
        // ------------------ geometry gate ------------------
        __shared__ __align__(16) float WgT[64][8];
        __shared__ __align__(16) float bgs[8];
        __shared__ float istat[2][6];

        const int b = bx >> 7, i2 = bx & 127;       // 16 b x 128 i-pairs
        const int iw = t >> 7, tj = t & 127;
        const int i = i2 * 2 + iw;

        for (int idx = t; idx < 512; idx += 256) {
            int g = idx >> 3, h = idx & 7;
            WgT[g][h] = Wg[h * 64 + g];
        }
        if (t < 8) bgs[t] = bg[t];
        if (t < 2) {
            float4 bxv = *(const float4*)&box[(b*NN + i2 * 2 + t) * 4];
            float cx = 0.5f * (bxv.x + bxv.z), cy = 0.5f * (bxv.y + bxv.w);
            float w = bxv.z - bxv.x + 1.0f,   h = bxv.w - bxv.y + 1.0f;
            istat[t][0] = cx; istat[t][1] = cy; istat[t][2] = w; istat[t][3] = h;
            istat[t][4] = __logf(w); istat[t][5] = __logf(h);
        }
        __syncthreads();

        const int j0 = tj * 2;
        float4 bj0 = *(const float4*)&box[(b*NN + j0) * 4];
        float4 bj1 = *(const float4*)&box[(b*NN + j0 + 1) * 4];

        const float icx = istat[iw][0], icy = istat[iw][1];
        const float iw2 = istat[iw][2], ih2 = istat[iw][3];
        const float ilw = istat[iw][4], ilh = istat[iw][5];

        float angA[4], angB[4];
        {
            float cxj = 0.5f * (bj0.x + bj0.z), cyj = 0.5f * (bj0.y + bj0.w);
            float wj = bj0.z - bj0.x + 1.0f,    hj = bj0.w - bj0.y + 1.0f;
            angA[0] = 100.0f * __logf(fmaxf(fabsf(icx - cxj) / iw2, 1e-3f));
            angA[1] = 100.0f * __logf(fmaxf(fabsf(icy - cyj) / ih2, 1e-3f));
            angA[2] = 100.0f * (ilw - __logf(wj));
            angA[3] = 100.0f * (ilh - __logf(hj));
        }
        {
            float cxj = 0.5f * (bj1.x + bj1.z), cyj = 0.5f * (bj1.y + bj1.w);
            float wj = bj1.z - bj1.x + 1.0f,    hj = bj1.w - bj1.y + 1.0f;
            angB[0] = 100.0f * __logf(fmaxf(fabsf(icx - cxj) / iw2, 1e-3f));
            angB[1] = 100.0f * __logf(fmaxf(fabsf(icy - cyj) / ih2, 1e-3f));
            angB[2] = 100.0f * (ilw - __logf(wj));
            angB[3] = 100.0f * (ilh - __logf(hj));
        }

        const float dimf[8] = {1.0f, 0.42169650342f, 0.17782794100f, 0.07498942093f,
                               0.03162277660f, 0.01333521432f, 0.00562341325f, 0.00237137371f};

        uint64_t A01 = *(const uint64_t*)&bgs[0], A23 = *(const uint64_t*)&bgs[2];
        uint64_t A45 = *(const uint64_t*)&bgs[4], A67 = *(const uint64_t*)&bgs[6];
        uint64_t B01 = A01, B23 = A23, B45 = A45, B67 = A67;

        #pragma unroll
        for (int g = 0; g < 32; g++) {
            const float df = dimf[g & 7];
            ulonglong2 wsA = *(const ulonglong2*)&WgT[g][0];
            ulonglong2 wsB = *(const ulonglong2*)&WgT[g][4];
            ulonglong2 wcA = *(const ulonglong2*)&WgT[32 + g][0];
            ulonglong2 wcB = *(const ulonglong2*)&WgT[32 + g][4];
            {
                float th = angA[g >> 3] * df;
                float n = rintf(th * 0.15915494309189535f);
                float r = fmaf(n, -6.283185482025146f, th);
                r = fmaf(n, 1.7484555e-7f, r);
                float s, co;
                __sincosf(r, &s, &co);
                uint64_t s2 = pack2(s), c2 = pack2(co);
                ffma2(A01, s2, wsA.x); ffma2(A23, s2, wsA.y);
                ffma2(A45, s2, wsB.x); ffma2(A67, s2, wsB.y);
                ffma2(A01, c2, wcA.x); ffma2(A23, c2, wcA.y);
                ffma2(A45, c2, wcB.x); ffma2(A67, c2, wcB.y);
            }
            {
                float th = angB[g >> 3] * df;
                float n = rintf(th * 0.15915494309189535f);
                float r = fmaf(n, -6.283185482025146f, th);
                r = fmaf(n, 1.7484555e-7f, r);
                float s, co;
                __sincosf(r, &s, &co);
                uint64_t s2 = pack2(s), c2 = pack2(co);
                ffma2(B01, s2, wsA.x); ffma2(B23, s2, wsA.y);
                ffma2(B45, s2, wsB.x); ffma2(B67, s2, wsB.y);
                ffma2(B01, c2, wcA.x); ffma2(B23, c2, wcA.y);
                ffma2(B45, c2, wcB.x); ffma2(B67, c2, wcB.y);
            }
        }

        float2 a01 = unpack2(A01), a23 = unpack2(A23), a45 = unpack2(A45), a67 = unpack2(A67);
        float2 b01 = unpack2(B01), b23 = unpack2(B23), b45 = unpack2(B45), b67 = unpack2(B67);
        float av[8] = {a01.x, a01.y, a23.x, a23.y, a45.x, a45.y, a67.x, a67.y};
        float bv[8] = {b01.x, b01.y, b23.x, b23.y, b45.x, b45.y, b67.x, b67.y};
        const int base = ((b*NH) * NN + i) * NN + j0;
        #pragma unroll
        for (int h = 0; h < 8; h++) {
            float2 o;
            o.x = __logf(fmaxf(av[h], 1e-6f));
            o.y = __logf(fmaxf(bv[h], 1e-6f));
            *(float2*)&g_wgl[base + h * (NN*NN)] = o;
        }
    } else if (bx < 3072) {
        // ------------------ weight transpose + split ------------------
        __shared__ float tile[32][33];
        const int wb = bx - 2048;
        const int z = wb >> 8, xy = wb & 255;
        const float* W = (z == 0) ? w0 : (z == 1) ? w1 : (z == 2) ? w2 : w3;
        __nv_bfloat16* Th = g_wTh + z * (DDIM * DDIM);
        __nv_bfloat16* Tl = g_wTl + z * (DDIM * DDIM);
        const int x0 = (xy & 15) * 32, y0 = (xy >> 4) * 32;
        const int tx = t & 31, ty = t >> 5;
        #pragma unroll
        for (int r = ty; r < 32; r += 8)
            tile[r][tx] = W[(y0 + r) * DDIM + x0 + tx];
        __syncthreads();
        #pragma unroll
        for (int r = ty; r < 32; r += 8) {
            float vv = tile[tx][r];
            __nv_bfloat16 h, l; bsplit1(vv, h, l);
            Th[(x0 + r) * DDIM + y0 + tx] = h;
            Tl[(x0 + r) * DDIM + y0 + tx] = l;
        }
    } else {
        // ------------------ input split ------------------
        const int idx = bx - 3072;            // 0..6143
        const int z = idx / 2048, blk = idx % 2048;
        const float* src = (z == 0) ? q : (z == 1) ? k : v;
        __nv_bfloat16* oh = g_ah + z * (MROWS * DDIM);
        __nv_bfloat16* ol = g_al + z * (MROWS * DDIM);
        const int i4 = blk * 256 + t;
        float4 f = ((const float4*)src)[i4];
        uint32_t h0, l0, h1, l1;
        bsplit2(f.x, f.y, h0, l0);
        bsplit2(f.z, f.w, h1, l1);
        ((uint2*)oh)[i4] = make_uint2(h0, h1);
        ((uint2*)ol)[i4] = make_uint2(l0, l1);
    }
}

// =================================================================================
// HMMA GEMM (bf16 split, 3 passes). BM=128, BN=64, BK=32, 3-stage, 2 CTAs/SM.
// =================================================================================
#define BK 32
#define STG 3
#define ROWB 80
#define MAT_A (128*ROWB)
#define MAT_Bb (64*ROWB)
#define STG_B (2*MAT_A + 2*MAT_Bb)
#define GDYN (STG*STG_B)

struct GArgs {
    const __nv_bfloat16 *Ah, *Al, *Bh, *Bl;
    const float* bias[3];
    float*       C[3];
    __nv_bfloat16 *Oh[3], *Ol[3];
    float scale[3];
    int mode[3];
};

__global__ __launch_bounds__(256, 2)
void gemm_hmma(const GArgs args)
{
    extern __shared__ char smraw[];
    const uint32_t sb = smem_u32(smraw);
    const int t = threadIdx.x, lane = t & 31, wid = t >> 5;
    const int wm = wid & 3, wn = wid >> 2;
    const int z = blockIdx.z;
    const int r0 = blockIdx.y * 128, c0 = blockIdx.x * 64;

    const __nv_bfloat16* pAh = args.Ah + (size_t)z * MROWS * DDIM;
    const __nv_bfloat16* pAl = args.Al + (size_t)z * MROWS * DDIM;
    const __nv_bfloat16* pBh = args.Bh + (size_t)z * DDIM * DDIM;
    const __nv_bfloat16* pBl = args.Bl + (size_t)z * DDIM * DDIM;
    const float* bias = args.bias[z];

    const int row_a = t >> 2, ch = t & 3;
    auto load_stage = [&](int kt) {
        uint32_t dstS = sb + (uint32_t)(kt % STG) * STG_B;
        int k0 = kt * BK + ch * 8;
        #pragma unroll
        for (int it = 0; it < 2; it++) {
            int row = row_a + it * 64;
            uint32_t d = dstS + row * ROWB + ch * 16;
            CPA16(d,          pAh + (r0 + row) * DDIM + k0);
            CPA16(d + MAT_A,  pAl + (r0 + row) * DDIM + k0);
        }
        uint32_t d2 = dstS + 2 * MAT_A + row_a * ROWB + ch * 16;
        CPA16(d2,           pBh + (c0 + row_a) * DDIM + k0);
        CPA16(d2 + MAT_Bb,  pBl + (c0 + row_a) * DDIM + k0);
        CPCOMMIT();
    };

    float acc[2][4][4];
    #pragma unroll
    for (int mt = 0; mt < 2; mt++)
        #pragma unroll
        for (int nt = 0; nt < 4; nt++)
            #pragma unroll
            for (int i = 0; i < 4; i++) acc[mt][nt][i] = 0.0f;

    load_stage(0);
    load_stage(1);

    const uint32_t aRowOff = (uint32_t)(wm * 32 + (lane & 15)) * ROWB;
    const uint32_t aColOff = (uint32_t)(((lane >> 4) & 1) << 4);
    const uint32_t bRowOff = (uint32_t)(wn * 32 + (((lane >> 4) & 1) << 3) + (lane & 7)) * ROWB;
    const uint32_t bColOff = (uint32_t)(((lane >> 3) & 1) << 4);

    for (int kt = 0; kt < DDIM / BK; kt++) {
        CPWAIT1();
        __syncthreads();
        if (kt + 2 < DDIM / BK) load_stage(kt + 2);
        const uint32_t SB = sb + (uint32_t)(kt % STG) * STG_B;
        #pragma unroll
        for (int kk = 0; kk < 2; kk++) {
            const uint32_t k16b = (uint32_t)(kk * 32);
            uint32_t ah[2][4], al[2][4], fbh[2][4], fbl[2][4];
            uint32_t aA = SB + aRowOff + k16b + aColOff;
            ldsm4(ah[0], aA);
            ldsm4(ah[1], aA + 16 * ROWB);
            ldsm4(al[0], aA + MAT_A);
            ldsm4(al[1], aA + MAT_A + 16 * ROWB);
            uint32_t bA = SB + 2 * MAT_A + bRowOff + k16b + bColOff;
            #pragma unroll
            for (int n16 = 0; n16 < 2; n16++) {
                ldsm4(fbh[n16], bA + n16 * 16 * ROWB);
                ldsm4(fbl[n16], bA + MAT_Bb + n16 * 16 * ROWB);
            }
            #pragma unroll
            for (int mt = 0; mt < 2; mt++)
                #pragma unroll
                for (int nt = 0; nt < 4; nt++) {
                    const uint32_t* bph = &fbh[nt >> 1][(nt & 1) * 2];
                    const uint32_t* bpl = &fbl[nt >> 1][(nt & 1) * 2];
                    mma16816(acc[mt][nt], ah[mt], bph[0], bph[1]);
                    mma16816(acc[mt][nt], ah[mt], bpl[0], bpl[1]);
                    mma16816(acc[mt][nt], al[mt], bph[0], bph[1]);
                }
        }
    }

    const int md = args.mode[z];
    const float sc = args.scale[z];
    #pragma unroll
    for (int mt = 0; mt < 2; mt++) {
        int row0 = r0 + wm * 32 + mt * 16 + (lane >> 2);
        #pragma unroll
        for (int nt = 0; nt < 4; nt++) {
            int col = c0 + wn * 32 + nt * 8 + (lane & 3) * 2;
            float2 bs = *(const float2*)&bias[col];
            float v0 = (acc[mt][nt][0] + bs.x) * sc;
            float v1 = (acc[mt][nt][1] + bs.y) * sc;
            float v2 = (acc[mt][nt][2] + bs.x) * sc;
            float v3 = (acc[mt][nt][3] + bs.y) * sc;
            if (md == 0) {
                float* C = args.C[z];
                *(float2*)&C[row0 * DDIM + col] = make_float2(v0, v1);
                *(float2*)&C[(row0 + 8) * DDIM + col] = make_float2(v2, v3);
            } else if (md == 1) {
                __nv_bfloat16* Oh = args.Oh[z]; __nv_bfloat16* Ol = args.Ol[z];
                int hh = col >> 6, d = col & 63;
                uint32_t u0h, u0l, u1h, u1l;
                bsplit2(v0, v1, u0h, u0l);
                bsplit2(v2, v3, u1h, u1l);
                int b0i = row0 >> 8, n0i = row0 & 255;
                size_t i0x = (size_t)(((b0i * NH + hh) * NN + n0i) * DKH + d);
                *(uint32_t*)(Oh + i0x) = u0h; *(uint32_t*)(Ol + i0x) = u0l;
                int r1i = row0 + 8;
                int b1i = r1i >> 8, n1i = r1i & 255;
                size_t i1x = (size_t)(((b1i * NH + hh) * NN + n1i) * DKH + d);
                *(uint32_t*)(Oh + i1x) = u1h; *(uint32_t*)(Ol + i1x) = u1l;
            } else {
                __nv_bfloat16* Oh = args.Oh[z]; __nv_bfloat16* Ol = args.Ol[z];
                int hh = col >> 6, d = col & 63;
                int b0i = row0 >> 8, n0i = row0 & 255;
                size_t base = (size_t)(((b0i * NH + hh) * DKH + d) * NN + n0i);
                __nv_bfloat16 h, l;
                bsplit1(v0, h, l); Oh[base] = h;           Ol[base] = l;
                bsplit1(v1, h, l); Oh[base + NN] = h;      Ol[base + NN] = l;
                bsplit1(v2, h, l); Oh[base + 8] = h;       Ol[base + 8] = l;
                bsplit1(v3, h, l); Oh[base + NN + 8] = h;  Ol[base + NN + 8] = l;
            }
        }
    }
}

// =================================================================================
// Flash attention (unchanged from R14)
// =================================================================================
#define AF_QH 0
#define AF_QL 16384
#define AF_KV 32768
#define AF_STAGE 32768
#define AF_TOT (AF_KV + 2*AF_STAGE)   // 98304

__global__ __launch_bounds__(256, 2)
void attn_flash()
{
    extern __shared__ char sm[];
    const uint32_t sb = smem_u32(sm);
    const int t = threadIdx.x, lane = t & 31, w = t >> 5;
    const int bh = blockIdx.x >> 1, half = blockIdx.x & 1;
    const __nv_bfloat16* kh = g_kh + (size_t)bh * NN * DKH;
    const __nv_bfloat16* kl = g_kl + (size_t)bh * NN * DKH;
    const __nv_bfloat16* vh = g_vh + (size_t)bh * DKH * NN;
    const __nv_bfloat16* vl = g_vl + (size_t)bh * DKH * NN;
    const __nv_bfloat16* qh = g_qh + (size_t)bh * NN * DKH + (size_t)half * 128 * DKH;
    const __nv_bfloat16* ql = g_ql + (size_t)bh * NN * DKH + (size_t)half * 128 * DKH;
    const float* wglb = g_wgl + (size_t)bh * NN * NN + (size_t)(half * 128) * NN;

    #pragma unroll
    for (int p = 0; p < 4; p++) {
        int idx = t + p * 256; int r = idx >> 3, c = idx & 7;
        uint32_t off = ((uint32_t)(r * 128 + c * 16)) ^ ((uint32_t)(r & 7) << 4);
        CPA16(sb + AF_QH + off, qh + r * 64 + c * 8);
        CPA16(sb + AF_QL + off, ql + r * 64 + c * 8);
    }
    auto load_kv = [&](int kt) {
        int j0 = kt * 64;
        uint32_t dst = sb + AF_KV + (uint32_t)(kt & 1) * AF_STAGE;
        #pragma unroll
        for (int p = 0; p < 2; p++) {
            int idx = t + p * 256; int r = idx >> 3, c = idx & 7;
            uint32_t off = ((uint32_t)(r * 128 + c * 16)) ^ ((uint32_t)(r & 7) << 4);
            CPA16(dst + off,          kh + (j0 + r) * 64 + c * 8);
            CPA16(dst + 8192 + off,   kl + (j0 + r) * 64 + c * 8);
            CPA16(dst + 16384 + off,  vh + r * 256 + j0 + c * 8);
            CPA16(dst + 24576 + off,  vl + r * 256 + j0 + c * 8);
        }
        CPCOMMIT();
    };
    load_kv(0);
    load_kv(1);

    const uint32_t swz = (uint32_t)(lane & 7) << 4;
    const uint32_t aoffBase = (uint32_t)((w * 16 + (lane & 15)) * 128 + ((lane >> 4) & 1) * 16);
    const uint32_t boffBase = (uint32_t)(((((lane >> 4) & 1) * 8) + (lane & 7)) * 128 + ((lane >> 3) & 1) * 16);

    float mprev0 = -1e30f, mprev1 = -1e30f;
    float ssum0 = 0.0f, ssum1 = 0.0f;
    float oacc[8][4];
    #pragma unroll
    for (int nt = 0; nt < 8; nt++)
        #pragma unroll
        for (int u = 0; u < 4; u++) oacc[nt][u] = 0.0f;

    #pragma unroll
    for (int kt = 0; kt < 4; kt++) {
        if (kt == 3) { CPWAIT0(); } else { CPWAIT1(); }
        __syncthreads();
        const uint32_t KB = sb + AF_KV + (uint32_t)(kt & 1) * AF_STAGE;

        float acc[8][4];
        #pragma unroll
        for (int nt = 0; nt < 8; nt++)
            #pragma unroll
            for (int u = 0; u < 4; u++) acc[nt][u] = 0.0f;

        #pragma unroll
        for (int ks = 0; ks < 4; ks++) {
            uint32_t ah[4], al[4];
            uint32_t aA = (aoffBase + (uint32_t)(ks * 32)) ^ swz;
            ldsm4(ah, sb + AF_QH + aA);
            ldsm4(al, sb + AF_QL + aA);
            uint32_t bA = (boffBase + (uint32_t)(ks * 32)) ^ swz;
            #pragma unroll
            for (int n16 = 0; n16 < 4; n16++) {
                uint32_t fbh[4], fbl[4];
                ldsm4(fbh, KB + bA + n16 * 2048);
                ldsm4(fbl, KB + 8192 + bA + n16 * 2048);
                #pragma unroll
                for (int q = 0; q < 2; q++) {
                    int nt = n16 * 2 + q;
                    mma16816(acc[nt], ah, fbh[q*2], fbh[q*2+1]);
                    mma16816(acc[nt], ah, fbl[q*2], fbl[q*2+1]);
                    mma16816(acc[nt], al, fbh[q*2], fbh[q*2+1]);
                }
            }
        }

        {
            int rA = w * 16 + (lane >> 2);
            const float* w0p = wglb + (size_t)rA * NN + kt * 64 + (lane & 3) * 2;
            const float* w1p = w0p + 8 * NN;
            #pragma unroll
            for (int nt = 0; nt < 8; nt++) {
                float2 g0 = *(const float2*)(w0p + nt * 8);
                float2 g1 = *(const float2*)(w1p + nt * 8);
                acc[nt][0] += g0.x; acc[nt][1] += g0.y;
                acc[nt][2] += g1.x; acc[nt][3] += g1.y;
            }
        }

        float mt0 = -1e30f, mt1 = -1e30f;
        #pragma unroll
        for (int nt = 0; nt < 8; nt++) {
            mt0 = fmaxf(mt0, fmaxf(acc[nt][0], acc[nt][1]));
            mt1 = fmaxf(mt1, fmaxf(acc[nt][2], acc[nt][3]));
        }
        #pragma unroll
        for (int off = 1; off <= 2; off <<= 1) {
            mt0 = fmaxf(mt0, __shfl_xor_sync(~0u, mt0, off));
            mt1 = fmaxf(mt1, __shfl_xor_sync(~0u, mt1, off));
        }
        float mn0 = fmaxf(mprev0, mt0), mn1 = fmaxf(mprev1, mt1);
        float f0 = __expf(mprev0 - mn0), f1 = __expf(mprev1 - mn1);
        mprev0 = mn0; mprev1 = mn1;
        float ls0 = 0.0f, ls1 = 0.0f;
        #pragma unroll
        for (int nt = 0; nt < 8; nt++) {
            acc[nt][0] = __expf(acc[nt][0] - mn0);
            acc[nt][1] = __expf(acc[nt][1] - mn0);
            acc[nt][2] = __expf(acc[nt][2] - mn1);
            acc[nt][3] = __expf(acc[nt][3] - mn1);
            ls0 += acc[nt][0] + acc[nt][1];
            ls1 += acc[nt][2] + acc[nt][3];
            oacc[nt][0] *= f0; oacc[nt][1] *= f0;
            oacc[nt][2] *= f1; oacc[nt][3] *= f1;
        }
        #pragma unroll
        for (int off = 1; off <= 2; off <<= 1) {
            ls0 += __shfl_xor_sync(~0u, ls0, off);
            ls1 += __shfl_xor_sync(~0u, ls1, off);
        }
        ssum0 = ssum0 * f0 + ls0;
        ssum1 = ssum1 * f1 + ls1;

        #pragma unroll
        for (int kt2 = 0; kt2 < 4; kt2++) {
            uint32_t aph[4], apl[4];
            bsplit2(acc[2*kt2][0],   acc[2*kt2][1],   aph[0], apl[0]);
            bsplit2(acc[2*kt2][2],   acc[2*kt2][3],   aph[1], apl[1]);
            bsplit2(acc[2*kt2+1][0], acc[2*kt2+1][1], aph[2], apl[2]);
            bsplit2(acc[2*kt2+1][2], acc[2*kt2+1][3], aph[3], apl[3]);
            uint32_t bA = (boffBase + (uint32_t)(kt2 * 32)) ^ swz;
            #pragma unroll
            for (int n16 = 0; n16 < 4; n16++) {
                uint32_t vbh[4], vbl[4];
                ldsm4(vbh, KB + 16384 + bA + n16 * 2048);
                ldsm4(vbl, KB + 24576 + bA + n16 * 2048);
                #pragma unroll
                for (int q = 0; q < 2; q++) {
                    int nt = n16 * 2 + q;
                    mma16816(oacc[nt], aph, vbh[q*2], vbh[q*2+1]);
                    mma16816(oacc[nt], aph, vbl[q*2], vbl[q*2+1]);
                    mma16816(oacc[nt], apl, vbh[q*2], vbh[q*2+1]);
                }
            }
        }
        __syncthreads();
        if (kt < 2) load_kv(kt + 2);
    }

    {
        float inv0 = 1.0f / ssum0, inv1 = 1.0f / ssum1;
        int rA = w * 16 + (lane >> 2);
        int orow = (bh >> 3) * NN + half * 128 + rA;
        int ocol = (bh & 7) * DKH + (lane & 3) * 2;
        #pragma unroll
        for (int nt = 0; nt < 8; nt++) {
            float v0 = oacc[nt][0] * inv0, v1 = oacc[nt][1] * inv0;
            float v2 = oacc[nt][2] * inv1, v3 = oacc[nt][3] * inv1;
            uint32_t h0, l0, h1, l1;
            bsplit2(v0, v1, h0, l0);
            bsplit2(v2, v3, h1, l1);
            size_t i0x = (size_t)orow * DDIM + ocol + nt * 8;
            size_t i1x = (size_t)(orow + 8) * DDIM + ocol + nt * 8;
            *(uint32_t*)(g_ah + i0x) = h0; *(uint32_t*)(g_al + i0x) = l0;
            *(uint32_t*)(g_ah + i1x) = h1; *(uint32_t*)(g_al + i1x) = l1;
        }
    }
}

// =================================================================================
// launch
// =================================================================================
extern "C" void kernel_launch(void* const* d_in, const int* in_sizes, int n_in,
                              void* d_out, int out_size)
{
    const float* query = (const float*)d_in[0];
    const float* key   = (const float*)d_in[1];
    const float* value = (const float*)d_in[2];
    const float* box   = (const float*)d_in[3];
    const float* Wq = (const float*)d_in[4];
    const float* bq = (const float*)d_in[5];
    const float* Wk = (const float*)d_in[6];
    const float* bk = (const float*)d_in[7];
    const float* Wv = (const float*)d_in[8];
    const float* bv = (const float*)d_in[9];
    const float* Wo = (const float*)d_in[10];
    const float* bo = (const float*)d_in[11];
    const float* Wg = (const float*)d_in[12];
    const float* bg = (const float*)d_in[13];
    float* out = (float*)d_out;

    __nv_bfloat16 *pah, *pal, *pwh, *pwl, *pqh, *pql, *pkh, *pkl, *pvh, *pvl;
    cudaGetSymbolAddress((void**)&pah, g_ah);
    cudaGetSymbolAddress((void**)&pal, g_al);
    cudaGetSymbolAddress((void**)&pwh, g_wTh);
    cudaGetSymbolAddress((void**)&pwl, g_wTl);
    cudaGetSymbolAddress((void**)&pqh, g_qh);
    cudaGetSymbolAddress((void**)&pql, g_ql);
    cudaGetSymbolAddress((void**)&pkh, g_kh);
    cudaGetSymbolAddress((void**)&pkl, g_kl);
    cudaGetSymbolAddress((void**)&pvh, g_vh);
    cudaGetSymbolAddress((void**)&pvl, g_vl);

    static bool attr_set = false;
    if (!attr_set) {
        cudaFuncSetAttribute(gemm_hmma, cudaFuncAttributeMaxDynamicSharedMemorySize, GDYN);
        cudaFuncSetAttribute(attn_flash, cudaFuncAttributeMaxDynamicSharedMemorySize, AF_TOT);
        attr_set = true;
    }

    // stage 1: wg (first, long pole) + weight transpose/split + input split in ONE launch
    stage1_kernel<<<9216, 256>>>(box, Wg, bg, Wq, Wk, Wv, Wo, query, key, value);

    GArgs ga;
    ga.Ah = pah; ga.Al = pal; ga.Bh = pwh; ga.Bl = pwl;
    ga.bias[0] = bq; ga.bias[1] = bk; ga.bias[2] = bv;
    ga.C[0] = ga.C[1] = ga.C[2] = nullptr;
    ga.Oh[0] = pqh; ga.Ol[0] = pql;
    ga.Oh[1] = pkh; ga.Ol[1] = pkl;
    ga.Oh[2] = pvh; ga.Ol[2] = pvl;
    ga.scale[0] = 0.125f; ga.scale[1] = 1.0f; ga.scale[2] = 1.0f;
    ga.mode[0] = 1; ga.mode[1] = 1; ga.mode[2] = 2;
    gemm_hmma<<<dim3(8, 32, 3), 256, GDYN>>>(ga);

    attn_flash<<<NB * NH * 2, 256, AF_TOT>>>();

    GArgs go;
    go.Ah = pah; go.Al = pal;
    go.Bh = pwh + 3 * DDIM * DDIM; go.Bl = pwl + 3 * DDIM * DDIM;
    go.bias[0] = go.bias[1] = go.bias[2] = bo;
    go.C[0] = go.C[1] = go.C[2] = out;
    go.Oh[0] = go.Oh[1] = go.Oh[2] = nullptr;
    go.Ol[0] = go.Ol[1] = go.Ol[2] = nullptr;
    go.scale[0] = go.scale[1] = go.scale[2] = 1.0f;
    go.mode[0] = go.mode[1] = go.mode[2] = 0;
    gemm_hmma<<<dim3(8, 32, 1), 256, GDYN>>>(go);
}